// round 1
// baseline (speedup 1.0000x reference)
#include <cuda_runtime.h>
#include <math.h>

#define B_   16
#define C_   512
#define N_   4096
#define NH_  8
#define HD_  64
#define NG_  8
#define CPG_ 64
#define EPS_ 1e-5f

// Scratch (allocation-free rule: static device globals)
__device__ float g_qkv[(size_t)B_ * 3 * C_ * N_];   // 384 MB  [b][3C][N]
__device__ float g_hv [(size_t)B_ * C_ * N_];       // 128 MB  [b][C][N]
__device__ float g_scale[B_ * C_];
__device__ float g_shift[B_ * C_];

// ---------------------------------------------------------------------------
// Kernel 1: group-norm statistics -> per (b,c) affine scale/shift
// grid = B*NG blocks, 256 threads
// ---------------------------------------------------------------------------
__global__ __launch_bounds__(256) void gn_stats_kernel(
    const float* __restrict__ x,
    const float* __restrict__ gamma,
    const float* __restrict__ beta)
{
    int bg = blockIdx.x;
    int b = bg / NG_, g = bg % NG_;
    const float4* xp = (const float4*)(x + ((size_t)b * C_ + (size_t)g * CPG_) * N_);
    const int total4 = CPG_ * N_ / 4;   // 65536

    float s = 0.f, ss = 0.f;
    for (int i = threadIdx.x; i < total4; i += 256) {
        float4 v = xp[i];
        s  += v.x + v.y + v.z + v.w;
        ss += v.x*v.x + v.y*v.y + v.z*v.z + v.w*v.w;
    }
    __shared__ float sh_s[256], sh_q[256];
    sh_s[threadIdx.x] = s; sh_q[threadIdx.x] = ss;
    __syncthreads();
    for (int off = 128; off > 0; off >>= 1) {
        if (threadIdx.x < off) {
            sh_s[threadIdx.x] += sh_s[threadIdx.x + off];
            sh_q[threadIdx.x] += sh_q[threadIdx.x + off];
        }
        __syncthreads();
    }
    float inv_n = 1.f / (float)(CPG_ * N_);
    float mean = sh_s[0] * inv_n;
    float var  = sh_q[0] * inv_n - mean * mean;
    float rstd = rsqrtf(var + EPS_);
    if (threadIdx.x < CPG_) {
        int c = g * CPG_ + threadIdx.x;
        float ga = gamma[c];
        g_scale[b * C_ + c] = rstd * ga;
        g_shift[b * C_ + c] = beta[c] - mean * rstd * ga;
    }
}

// ---------------------------------------------------------------------------
// SGEMM config: 128x128 tile, BK=16, 256 threads, 8x8 per thread
// ---------------------------------------------------------------------------
#define BM 128
#define BN 128
#define BK 16
#define TM 8
#define TN 8

// Kernel 2: qkv[b][o][n] = sum_c W[o][c]*(x[b][c][n]*scale+shift) + b_qkv[o]
__global__ __launch_bounds__(256) void qkv_gemm_kernel(
    const float* __restrict__ x,
    const float* __restrict__ W,
    const float* __restrict__ bias)
{
    int b  = blockIdx.z;
    int bm = blockIdx.y;
    int bn = blockIdx.x;
    __shared__ float As[BK][BM];   // A transposed: As[c][o]
    __shared__ float Bs[BK][BN];

    const float* xb  = x + (size_t)b * C_ * N_;
    const float* scl = g_scale + b * C_;
    const float* shf = g_shift + b * C_;

    int tid  = threadIdx.x;
    int trow = (tid >> 4) * TM;       // 0..120
    int tcol = (tid & 15) * TN;       // 0..120

    float acc[TM][TN];
    #pragma unroll
    for (int i = 0; i < TM; i++)
        #pragma unroll
        for (int j = 0; j < TN; j++) acc[i][j] = 0.f;

    for (int k0 = 0; k0 < C_; k0 += BK) {
        #pragma unroll
        for (int l = 0; l < 2; l++) {
            int idx = tid + l * 256;              // 0..511
            int row = idx >> 2;                   // o in tile
            int cc  = (idx & 3) << 2;             // c in tile
            float4 wv = *(const float4*)(W + (size_t)(bm * BM + row) * C_ + k0 + cc);
            As[cc + 0][row] = wv.x;
            As[cc + 1][row] = wv.y;
            As[cc + 2][row] = wv.z;
            As[cc + 3][row] = wv.w;
        }
        #pragma unroll
        for (int l = 0; l < 2; l++) {
            int idx = tid + l * 256;
            int row = idx >> 5;                   // c in tile (0..15)
            int col = (idx & 31) << 2;            // n in tile
            int c = k0 + row;
            float sc = scl[c], sf = shf[c];
            float4 xv = *(const float4*)(xb + (size_t)c * N_ + bn * BN + col);
            float4 bv = make_float4(xv.x*sc+sf, xv.y*sc+sf, xv.z*sc+sf, xv.w*sc+sf);
            *(float4*)&Bs[row][col] = bv;
        }
        __syncthreads();
        #pragma unroll
        for (int k = 0; k < BK; k++) {
            float ra[TM], rb[TN];
            *(float4*)&ra[0] = *(const float4*)&As[k][trow];
            *(float4*)&ra[4] = *(const float4*)&As[k][trow + 4];
            *(float4*)&rb[0] = *(const float4*)&Bs[k][tcol];
            *(float4*)&rb[4] = *(const float4*)&Bs[k][tcol + 4];
            #pragma unroll
            for (int i = 0; i < TM; i++)
                #pragma unroll
                for (int j = 0; j < TN; j++)
                    acc[i][j] += ra[i] * rb[j];
        }
        __syncthreads();
    }

    float* out = g_qkv + ((size_t)b * 3 * C_ + (size_t)(bm * BM)) * N_ + bn * BN;
    #pragma unroll
    for (int i = 0; i < TM; i++) {
        float bi = bias[bm * BM + trow + i];
        #pragma unroll
        for (int j = 0; j < TN; j += 4) {
            float4 v = make_float4(acc[i][j]+bi, acc[i][j+1]+bi, acc[i][j+2]+bi, acc[i][j+3]+bi);
            *(float4*)(out + (size_t)(trow + i) * N_ + tcol + j) = v;
        }
    }
}

// Kernel 4: out[b][o][n] = sum_c Wo[o][c]*hv[b][c][n] + b_out[o] + x[b][o][n]
__global__ __launch_bounds__(256) void out_gemm_kernel(
    const float* __restrict__ W,
    const float* __restrict__ bias,
    const float* __restrict__ x,
    float* __restrict__ out)
{
    int b  = blockIdx.z;
    int bm = blockIdx.y;
    int bn = blockIdx.x;
    __shared__ float As[BK][BM];
    __shared__ float Bs[BK][BN];

    const float* hb = g_hv + (size_t)b * C_ * N_;

    int tid  = threadIdx.x;
    int trow = (tid >> 4) * TM;
    int tcol = (tid & 15) * TN;

    float acc[TM][TN];
    #pragma unroll
    for (int i = 0; i < TM; i++)
        #pragma unroll
        for (int j = 0; j < TN; j++) acc[i][j] = 0.f;

    for (int k0 = 0; k0 < C_; k0 += BK) {
        #pragma unroll
        for (int l = 0; l < 2; l++) {
            int idx = tid + l * 256;
            int row = idx >> 2;
            int cc  = (idx & 3) << 2;
            float4 wv = *(const float4*)(W + (size_t)(bm * BM + row) * C_ + k0 + cc);
            As[cc + 0][row] = wv.x;
            As[cc + 1][row] = wv.y;
            As[cc + 2][row] = wv.z;
            As[cc + 3][row] = wv.w;
        }
        #pragma unroll
        for (int l = 0; l < 2; l++) {
            int idx = tid + l * 256;
            int row = idx >> 5;
            int col = (idx & 31) << 2;
            *(float4*)&Bs[row][col] =
                *(const float4*)(hb + (size_t)(k0 + row) * N_ + bn * BN + col);
        }
        __syncthreads();
        #pragma unroll
        for (int k = 0; k < BK; k++) {
            float ra[TM], rb[TN];
            *(float4*)&ra[0] = *(const float4*)&As[k][trow];
            *(float4*)&ra[4] = *(const float4*)&As[k][trow + 4];
            *(float4*)&rb[0] = *(const float4*)&Bs[k][tcol];
            *(float4*)&rb[4] = *(const float4*)&Bs[k][tcol + 4];
            #pragma unroll
            for (int i = 0; i < TM; i++)
                #pragma unroll
                for (int j = 0; j < TN; j++)
                    acc[i][j] += ra[i] * rb[j];
        }
        __syncthreads();
    }

    const float* xr = x + ((size_t)b * C_ + (size_t)(bm * BM)) * N_ + bn * BN;
    float* outp = out + ((size_t)b * C_ + (size_t)(bm * BM)) * N_ + bn * BN;
    #pragma unroll
    for (int i = 0; i < TM; i++) {
        float bi = bias[bm * BM + trow + i];
        #pragma unroll
        for (int j = 0; j < TN; j += 4) {
            float4 xv = *(const float4*)(xr + (size_t)(trow + i) * N_ + tcol + j);
            float4 v = make_float4(acc[i][j]+bi+xv.x, acc[i][j+1]+bi+xv.y,
                                   acc[i][j+2]+bi+xv.z, acc[i][j+3]+bi+xv.w);
            *(float4*)(outp + (size_t)(trow + i) * N_ + tcol + j) = v;
        }
    }
}

// ---------------------------------------------------------------------------
// Kernel 3: attention per (b,h): S = q k^T (64x64 over N=4096), softmax rows,
// hv = P v. XOR-swizzled smem tiles (16-float4 groups) for conflict-free LDS.
// grid = B*NH = 128 blocks, 256 threads
// ---------------------------------------------------------------------------
__device__ __forceinline__ int swz(int row, int col4) {
    return (row * 16 + (col4 ^ ((row >> 2) & 15))) * 4;   // float index
}

__global__ __launch_bounds__(256) void attn_kernel()
{
    __shared__ float sA[64 * 68];   // q swz (4096) -> S plain (pad 68) -> v swz
    __shared__ float sB[64 * 64];   // k swz -> P swz

    int bh = blockIdx.x;
    int b = bh / NH_, h = bh % NH_;
    const float* q = g_qkv + ((size_t)b * 3 * C_ + 0 * C_ + (size_t)h * HD_) * N_;
    const float* k = g_qkv + ((size_t)b * 3 * C_ + 1 * C_ + (size_t)h * HD_) * N_;
    const float* v = g_qkv + ((size_t)b * 3 * C_ + 2 * C_ + (size_t)h * HD_) * N_;
    float* hv = g_hv + ((size_t)b * C_ + (size_t)h * HD_) * N_;

    int tid = threadIdx.x;
    int td = (tid >> 4) * 4;   // d-tile base (0..60)
    int te = (tid & 15) * 4;   // e-tile / n-tile base (0..60)

    // ---------- Phase A: S[d][e] = sum_n q[d][n] k[e][n] ----------
    float acc[4][4];
    #pragma unroll
    for (int i = 0; i < 4; i++)
        #pragma unroll
        for (int j = 0; j < 4; j++) acc[i][j] = 0.f;

    for (int n0 = 0; n0 < N_; n0 += 64) {
        #pragma unroll
        for (int l = 0; l < 4; l++) {
            int idx = tid + l * 256;       // 0..1023
            int row = idx >> 4;            // 0..63
            int c4  = idx & 15;
            *(float4*)(sA + swz(row, c4)) = *(const float4*)(q + (size_t)row * N_ + n0 + c4 * 4);
            *(float4*)(sB + swz(row, c4)) = *(const float4*)(k + (size_t)row * N_ + n0 + c4 * 4);
        }
        __syncthreads();
        #pragma unroll 4
        for (int c4 = 0; c4 < 16; c4++) {
            float4 ra[4], rb[4];
            #pragma unroll
            for (int i = 0; i < 4; i++) ra[i] = *(const float4*)(sA + swz(td + i, c4));
            #pragma unroll
            for (int j = 0; j < 4; j++) rb[j] = *(const float4*)(sB + swz(te + j, c4));
            #pragma unroll
            for (int i = 0; i < 4; i++)
                #pragma unroll
                for (int j = 0; j < 4; j++)
                    acc[i][j] += ra[i].x*rb[j].x + ra[i].y*rb[j].y
                               + ra[i].z*rb[j].z + ra[i].w*rb[j].w;
        }
        __syncthreads();
    }

    // write S * scale (plain layout, pad 68) into sA
    const float scale = 0.125f;   // 1/sqrt(64)
    #pragma unroll
    for (int i = 0; i < 4; i++) {
        float4 sv = make_float4(acc[i][0]*scale, acc[i][1]*scale,
                                acc[i][2]*scale, acc[i][3]*scale);
        *(float4*)(sA + (td + i) * 68 + te) = sv;
    }
    __syncthreads();

    // ---------- Phase B: row softmax; P (swizzled) -> sB ----------
    if (tid < 64) {
        int r = tid;
        float m = -1e30f;
        for (int c = 0; c < 64; c++) m = fmaxf(m, sA[r * 68 + c]);
        float s = 0.f;
        for (int c = 0; c < 64; c++) {
            float e = __expf(sA[r * 68 + c] - m);
            sA[r * 68 + c] = e;
            s += e;
        }
        float inv = 1.f / s;
        for (int c4 = 0; c4 < 16; c4++) {
            float4 p = *(const float4*)(sA + r * 68 + c4 * 4);
            p.x *= inv; p.y *= inv; p.z *= inv; p.w *= inv;
            *(float4*)(sB + swz(r, c4)) = p;
        }
    }
    __syncthreads();

    // ---------- Phase C: hv[d][n] = sum_e P[d][e] v[e][n] ----------
    for (int n0 = 0; n0 < N_; n0 += 64) {
        #pragma unroll
        for (int l = 0; l < 4; l++) {
            int idx = tid + l * 256;
            int row = idx >> 4;
            int c4  = idx & 15;
            *(float4*)(sA + swz(row, c4)) = *(const float4*)(v + (size_t)row * N_ + n0 + c4 * 4);
        }
        __syncthreads();

        float a2[4][4];
        #pragma unroll
        for (int i = 0; i < 4; i++)
            #pragma unroll
            for (int j = 0; j < 4; j++) a2[i][j] = 0.f;

        #pragma unroll 4
        for (int e4 = 0; e4 < 16; e4++) {
            float4 pa[4], vb[4];
            #pragma unroll
            for (int i = 0; i < 4; i++) pa[i] = *(const float4*)(sB + swz(td + i, e4));
            #pragma unroll
            for (int m = 0; m < 4; m++) vb[m] = *(const float4*)(sA + swz(e4 * 4 + m, te >> 2 ? (te >> 2) : 0));
            // NOTE: col4 for v is te/4 — rewritten explicitly below to avoid confusion
            #pragma unroll
            for (int m = 0; m < 4; m++) vb[m] = *(const float4*)(sA + swz(e4 * 4 + m, te >> 2));
            #pragma unroll
            for (int i = 0; i < 4; i++) {
                a2[i][0] += pa[i].x*vb[0].x + pa[i].y*vb[1].x + pa[i].z*vb[2].x + pa[i].w*vb[3].x;
                a2[i][1] += pa[i].x*vb[0].y + pa[i].y*vb[1].y + pa[i].z*vb[2].y + pa[i].w*vb[3].y;
                a2[i][2] += pa[i].x*vb[0].z + pa[i].y*vb[1].z + pa[i].z*vb[2].z + pa[i].w*vb[3].z;
                a2[i][3] += pa[i].x*vb[0].w + pa[i].y*vb[1].w + pa[i].z*vb[2].w + pa[i].w*vb[3].w;
            }
        }
        #pragma unroll
        for (int i = 0; i < 4; i++) {
            float4 o = make_float4(a2[i][0], a2[i][1], a2[i][2], a2[i][3]);
            *(float4*)(hv + (size_t)(td + i) * N_ + n0 + te) = o;
        }
        __syncthreads();
    }
}

// ---------------------------------------------------------------------------
extern "C" void kernel_launch(void* const* d_in, const int* in_sizes, int n_in,
                              void* d_out, int out_size)
{
    const float* x     = (const float*)d_in[0];
    const float* gamma = (const float*)d_in[1];
    const float* beta  = (const float*)d_in[2];
    const float* w_qkv = (const float*)d_in[3];
    const float* b_qkv = (const float*)d_in[4];
    const float* w_out = (const float*)d_in[5];
    const float* b_out = (const float*)d_in[6];
    float* out = (float*)d_out;

    gn_stats_kernel<<<B_ * NG_, 256>>>(x, gamma, beta);
    qkv_gemm_kernel<<<dim3(N_ / BN, (3 * C_) / BM, B_), 256>>>(x, w_qkv, b_qkv);
    attn_kernel<<<B_ * NH_, 256>>>();
    out_gemm_kernel<<<dim3(N_ / BN, C_ / BM, B_), 256>>>(w_out, b_out, x, out);
}

// round 2
// speedup vs baseline: 1.2373x; 1.2373x over previous
#include <cuda_runtime.h>
#include <math.h>
#include <stdint.h>

#define B_   16
#define C_   512
#define N_   4096
#define NH_  8
#define HD_  64
#define NG_  8
#define CPG_ 64
#define EPS_ 1e-5f

// Scratch (allocation-free rule: static device globals)
__device__ float g_qkv[(size_t)B_ * 3 * C_ * N_];   // 384 MB  [b][3C][N]
__device__ float g_hv [(size_t)B_ * C_ * N_];       // 128 MB  [b][C][N]
__device__ float g_scale[B_ * C_];
__device__ float g_shift[B_ * C_];

// ---------------------------------------------------------------------------
// Kernel 1: group-norm statistics -> per (b,c) affine scale/shift
// ---------------------------------------------------------------------------
__global__ __launch_bounds__(256) void gn_stats_kernel(
    const float* __restrict__ x,
    const float* __restrict__ gamma,
    const float* __restrict__ beta)
{
    int bg = blockIdx.x;
    int b = bg / NG_, g = bg % NG_;
    const float4* xp = (const float4*)(x + ((size_t)b * C_ + (size_t)g * CPG_) * N_);
    const int total4 = CPG_ * N_ / 4;

    float s = 0.f, ss = 0.f;
    for (int i = threadIdx.x; i < total4; i += 256) {
        float4 v = xp[i];
        s  += v.x + v.y + v.z + v.w;
        ss += v.x*v.x + v.y*v.y + v.z*v.z + v.w*v.w;
    }
    __shared__ float sh_s[256], sh_q[256];
    sh_s[threadIdx.x] = s; sh_q[threadIdx.x] = ss;
    __syncthreads();
    for (int off = 128; off > 0; off >>= 1) {
        if (threadIdx.x < off) {
            sh_s[threadIdx.x] += sh_s[threadIdx.x + off];
            sh_q[threadIdx.x] += sh_q[threadIdx.x + off];
        }
        __syncthreads();
    }
    float inv_n = 1.f / (float)(CPG_ * N_);
    float mean = sh_s[0] * inv_n;
    float var  = sh_q[0] * inv_n - mean * mean;
    float rstd = rsqrtf(var + EPS_);
    if (threadIdx.x < CPG_) {
        int c = g * CPG_ + threadIdx.x;
        float ga = gamma[c];
        g_scale[b * C_ + c] = rstd * ga;
        g_shift[b * C_ + c] = beta[c] - mean * rstd * ga;
    }
}

// ---------------------------------------------------------------------------
// tf32 tensor-core GEMM: 128x128 block tile, BK=32, 8 warps of 64x32
// ---------------------------------------------------------------------------
__device__ __forceinline__ float to_tf32(float x) {
    uint32_t u;
    asm("cvt.rna.tf32.f32 %0, %1;" : "=r"(u) : "f"(x));
    return __uint_as_float(u);
}

__device__ __forceinline__ void mma8(float c[4],
                                     float a0, float a1, float a2, float a3,
                                     float b0, float b1)
{
    asm volatile(
        "mma.sync.aligned.m16n8k8.row.col.f32.tf32.tf32.f32 "
        "{%0,%1,%2,%3}, {%4,%5,%6,%7}, {%8,%9}, {%0,%1,%2,%3};\n"
        : "+f"(c[0]), "+f"(c[1]), "+f"(c[2]), "+f"(c[3])
        : "r"(__float_as_uint(a0)), "r"(__float_as_uint(a1)),
          "r"(__float_as_uint(a2)), "r"(__float_as_uint(a3)),
          "r"(__float_as_uint(b0)), "r"(__float_as_uint(b1)));
}

// MODE 0: qkv  — B = groupnorm(x), Out = g_qkv, epilogue = +bias
// MODE 1: out  — B = g_hv,        Out = param,  epilogue = +bias +x residual
template<int MODE>
__global__ __launch_bounds__(256, 1) void gemm_tc(
    const float* __restrict__ W,
    const float* __restrict__ Bsrc_x,     // x (MODE 0) / unused (MODE 1)
    const float* __restrict__ bias,
    const float* __restrict__ resid,      // x (MODE 1)
    float* __restrict__ Out)              // d_out (MODE 1)
{
    int b  = blockIdx.z;
    int bm = blockIdx.y;
    int bn = blockIdx.x;

    __shared__ float As[128][40];    // [m][k], pad 8: frag loads conflict-free
    __shared__ float Bs[32][136];    // [k][n], pad 8: frag loads conflict-free

    const float* Bb = (MODE == 0) ? (Bsrc_x + (size_t)b * C_ * N_)
                                  : (g_hv   + (size_t)b * C_ * N_);
    const float* scl = g_scale + b * C_;
    const float* shf = g_shift + b * C_;

    int tid  = threadIdx.x;
    int lane = tid & 31;
    int wid  = tid >> 5;
    int gid  = lane >> 2;     // 0..7
    int tig  = lane & 3;      // 0..3
    int m_warp = (wid >> 2) * 64;   // 0 or 64
    int n_warp = (wid & 3) * 32;    // 0,32,64,96

    float acc[4][4][4];
    #pragma unroll
    for (int mt = 0; mt < 4; mt++)
        #pragma unroll
        for (int nt = 0; nt < 4; nt++)
            #pragma unroll
            for (int r = 0; r < 4; r++) acc[mt][nt][r] = 0.f;

    float4 ra[4], rb[4];

    // prefetch k0 = 0
    #pragma unroll
    for (int l = 0; l < 4; l++) {
        int idx = tid + l * 256;
        int m = idx >> 3, k4 = idx & 7;
        ra[l] = *(const float4*)(W + (size_t)(bm * 128 + m) * C_ + k4 * 4);
    }
    #pragma unroll
    for (int l = 0; l < 4; l++) {
        int idx = tid + l * 256;
        int k = idx >> 5, n4 = idx & 31;
        rb[l] = *(const float4*)(Bb + (size_t)k * N_ + bn * 128 + n4 * 4);
    }

    for (int k0 = 0; k0 < C_; k0 += 32) {
        // stage into smem (with tf32 convert; MODE 0 applies groupnorm affine)
        #pragma unroll
        for (int l = 0; l < 4; l++) {
            int idx = tid + l * 256;
            int m = idx >> 3, k4 = idx & 7;
            float4 v = ra[l];
            *(float4*)&As[m][k4 * 4] =
                make_float4(to_tf32(v.x), to_tf32(v.y), to_tf32(v.z), to_tf32(v.w));
        }
        #pragma unroll
        for (int l = 0; l < 4; l++) {
            int idx = tid + l * 256;
            int k = idx >> 5, n4 = idx & 31;
            float4 v = rb[l];
            if (MODE == 0) {
                float sc = scl[k0 + k], sf = shf[k0 + k];
                v.x = v.x * sc + sf; v.y = v.y * sc + sf;
                v.z = v.z * sc + sf; v.w = v.w * sc + sf;
            }
            *(float4*)&Bs[k][n4 * 4] =
                make_float4(to_tf32(v.x), to_tf32(v.y), to_tf32(v.z), to_tf32(v.w));
        }
        __syncthreads();

        // prefetch next tile while computing on this one
        if (k0 + 32 < C_) {
            #pragma unroll
            for (int l = 0; l < 4; l++) {
                int idx = tid + l * 256;
                int m = idx >> 3, k4 = idx & 7;
                ra[l] = *(const float4*)(W + (size_t)(bm * 128 + m) * C_ + k0 + 32 + k4 * 4);
            }
            #pragma unroll
            for (int l = 0; l < 4; l++) {
                int idx = tid + l * 256;
                int k = idx >> 5, n4 = idx & 31;
                rb[l] = *(const float4*)(Bb + (size_t)(k0 + 32 + k) * N_ + bn * 128 + n4 * 4);
            }
        }

        #pragma unroll
        for (int ks = 0; ks < 4; ks++) {
            int kb = ks * 8;
            float af[4][4], bf[4][2];
            #pragma unroll
            for (int mt = 0; mt < 4; mt++) {
                int m0 = m_warp + mt * 16 + gid;
                af[mt][0] = As[m0][kb + tig];
                af[mt][1] = As[m0 + 8][kb + tig];
                af[mt][2] = As[m0][kb + tig + 4];
                af[mt][3] = As[m0 + 8][kb + tig + 4];
            }
            #pragma unroll
            for (int nt = 0; nt < 4; nt++) {
                int n0 = n_warp + nt * 8 + gid;
                bf[nt][0] = Bs[kb + tig][n0];
                bf[nt][1] = Bs[kb + tig + 4][n0];
            }
            #pragma unroll
            for (int mt = 0; mt < 4; mt++)
                #pragma unroll
                for (int nt = 0; nt < 4; nt++)
                    mma8(acc[mt][nt], af[mt][0], af[mt][1], af[mt][2], af[mt][3],
                         bf[nt][0], bf[nt][1]);
        }
        __syncthreads();
    }

    // epilogue
    #pragma unroll
    for (int mt = 0; mt < 4; mt++) {
        int r0  = m_warp + mt * 16 + gid;
        int gr0 = bm * 128 + r0;
        float bi0 = bias[gr0];
        float bi1 = bias[gr0 + 8];
        #pragma unroll
        for (int nt = 0; nt < 4; nt++) {
            int col = n_warp + nt * 8 + tig * 2;
            if (MODE == 0) {
                float* o = g_qkv + ((size_t)b * 3 * C_ + gr0) * N_ + bn * 128 + col;
                *(float2*)o            = make_float2(acc[mt][nt][0] + bi0, acc[mt][nt][1] + bi0);
                *(float2*)(o + 8 * N_) = make_float2(acc[mt][nt][2] + bi1, acc[mt][nt][3] + bi1);
            } else {
                size_t base = ((size_t)b * C_ + gr0) * N_ + bn * 128 + col;
                float2 x0 = *(const float2*)(resid + base);
                float2 x1 = *(const float2*)(resid + base + 8 * N_);
                *(float2*)(Out + base) =
                    make_float2(acc[mt][nt][0] + bi0 + x0.x, acc[mt][nt][1] + bi0 + x0.y);
                *(float2*)(Out + base + 8 * N_) =
                    make_float2(acc[mt][nt][2] + bi1 + x1.x, acc[mt][nt][3] + bi1 + x1.y);
            }
        }
    }
}

// ---------------------------------------------------------------------------
// Kernel 3: attention per (b,h): S = q k^T (64x64 over N=4096), softmax rows,
// hv = P v. XOR-swizzled smem tiles for conflict-free LDS.
// ---------------------------------------------------------------------------
__device__ __forceinline__ int swz(int row, int col4) {
    return (row * 16 + (col4 ^ ((row >> 2) & 15))) * 4;   // float index
}

__global__ __launch_bounds__(256) void attn_kernel()
{
    __shared__ float sA[64 * 68];   // q swz -> S plain (pad 68) -> v swz
    __shared__ float sB[64 * 64];   // k swz -> P swz

    int bh = blockIdx.x;
    int b = bh / NH_, h = bh % NH_;
    const float* q = g_qkv + ((size_t)b * 3 * C_ + 0 * C_ + (size_t)h * HD_) * N_;
    const float* k = g_qkv + ((size_t)b * 3 * C_ + 1 * C_ + (size_t)h * HD_) * N_;
    const float* v = g_qkv + ((size_t)b * 3 * C_ + 2 * C_ + (size_t)h * HD_) * N_;
    float* hv = g_hv + ((size_t)b * C_ + (size_t)h * HD_) * N_;

    int tid = threadIdx.x;
    int td = (tid >> 4) * 4;
    int te = (tid & 15) * 4;

    float acc[4][4];
    #pragma unroll
    for (int i = 0; i < 4; i++)
        #pragma unroll
        for (int j = 0; j < 4; j++) acc[i][j] = 0.f;

    for (int n0 = 0; n0 < N_; n0 += 64) {
        #pragma unroll
        for (int l = 0; l < 4; l++) {
            int idx = tid + l * 256;
            int row = idx >> 4;
            int c4  = idx & 15;
            *(float4*)(sA + swz(row, c4)) = *(const float4*)(q + (size_t)row * N_ + n0 + c4 * 4);
            *(float4*)(sB + swz(row, c4)) = *(const float4*)(k + (size_t)row * N_ + n0 + c4 * 4);
        }
        __syncthreads();
        #pragma unroll 4
        for (int c4 = 0; c4 < 16; c4++) {
            float4 raf[4], rbf[4];
            #pragma unroll
            for (int i = 0; i < 4; i++) raf[i] = *(const float4*)(sA + swz(td + i, c4));
            #pragma unroll
            for (int j = 0; j < 4; j++) rbf[j] = *(const float4*)(sB + swz(te + j, c4));
            #pragma unroll
            for (int i = 0; i < 4; i++)
                #pragma unroll
                for (int j = 0; j < 4; j++)
                    acc[i][j] += raf[i].x*rbf[j].x + raf[i].y*rbf[j].y
                               + raf[i].z*rbf[j].z + raf[i].w*rbf[j].w;
        }
        __syncthreads();
    }

    const float scale = 0.125f;
    #pragma unroll
    for (int i = 0; i < 4; i++) {
        float4 sv = make_float4(acc[i][0]*scale, acc[i][1]*scale,
                                acc[i][2]*scale, acc[i][3]*scale);
        *(float4*)(sA + (td + i) * 68 + te) = sv;
    }
    __syncthreads();

    if (tid < 64) {
        int r = tid;
        float m = -1e30f;
        for (int c = 0; c < 64; c++) m = fmaxf(m, sA[r * 68 + c]);
        float s = 0.f;
        for (int c = 0; c < 64; c++) {
            float e = __expf(sA[r * 68 + c] - m);
            sA[r * 68 + c] = e;
            s += e;
        }
        float inv = 1.f / s;
        for (int c4 = 0; c4 < 16; c4++) {
            float4 p = *(const float4*)(sA + r * 68 + c4 * 4);
            p.x *= inv; p.y *= inv; p.z *= inv; p.w *= inv;
            *(float4*)(sB + swz(r, c4)) = p;
        }
    }
    __syncthreads();

    for (int n0 = 0; n0 < N_; n0 += 64) {
        #pragma unroll
        for (int l = 0; l < 4; l++) {
            int idx = tid + l * 256;
            int row = idx >> 4;
            int c4  = idx & 15;
            *(float4*)(sA + swz(row, c4)) = *(const float4*)(v + (size_t)row * N_ + n0 + c4 * 4);
        }
        __syncthreads();

        float a2[4][4];
        #pragma unroll
        for (int i = 0; i < 4; i++)
            #pragma unroll
            for (int j = 0; j < 4; j++) a2[i][j] = 0.f;

        #pragma unroll 4
        for (int e4 = 0; e4 < 16; e4++) {
            float4 pa[4], vb[4];
            #pragma unroll
            for (int i = 0; i < 4; i++) pa[i] = *(const float4*)(sB + swz(td + i, e4));
            #pragma unroll
            for (int m = 0; m < 4; m++) vb[m] = *(const float4*)(sA + swz(e4 * 4 + m, te >> 2));
            #pragma unroll
            for (int i = 0; i < 4; i++) {
                a2[i][0] += pa[i].x*vb[0].x + pa[i].y*vb[1].x + pa[i].z*vb[2].x + pa[i].w*vb[3].x;
                a2[i][1] += pa[i].x*vb[0].y + pa[i].y*vb[1].y + pa[i].z*vb[2].y + pa[i].w*vb[3].y;
                a2[i][2] += pa[i].x*vb[0].z + pa[i].y*vb[1].z + pa[i].z*vb[2].z + pa[i].w*vb[3].z;
                a2[i][3] += pa[i].x*vb[0].w + pa[i].y*vb[1].w + pa[i].z*vb[2].w + pa[i].w*vb[3].w;
            }
        }
        #pragma unroll
        for (int i = 0; i < 4; i++) {
            float4 o = make_float4(a2[i][0], a2[i][1], a2[i][2], a2[i][3]);
            *(float4*)(hv + (size_t)(td + i) * N_ + n0 + te) = o;
        }
        __syncthreads();
    }
}

// ---------------------------------------------------------------------------
extern "C" void kernel_launch(void* const* d_in, const int* in_sizes, int n_in,
                              void* d_out, int out_size)
{
    const float* x     = (const float*)d_in[0];
    const float* gamma = (const float*)d_in[1];
    const float* beta  = (const float*)d_in[2];
    const float* w_qkv = (const float*)d_in[3];
    const float* b_qkv = (const float*)d_in[4];
    const float* w_out = (const float*)d_in[5];
    const float* b_out = (const float*)d_in[6];
    float* out = (float*)d_out;

    gn_stats_kernel<<<B_ * NG_, 256>>>(x, gamma, beta);
    gemm_tc<0><<<dim3(N_ / 128, (3 * C_) / 128, B_), 256>>>(w_qkv, x, b_qkv, nullptr, nullptr);
    attn_kernel<<<B_ * NH_, 256>>>();
    gemm_tc<1><<<dim3(N_ / 128, C_ / 128, B_), 256>>>(w_out, nullptr, b_out, x, out);
}

// round 3
// speedup vs baseline: 2.7088x; 2.1892x over previous
#include <cuda_runtime.h>
#include <math.h>
#include <stdint.h>

#define B_   16
#define C_   512
#define N_   4096
#define NH_  8
#define HD_  64
#define NG_  8
#define CPG_ 64
#define EPS_ 1e-5f

// Scratch (allocation-free rule: static device globals)
__device__ float g_qkv[(size_t)B_ * 3 * C_ * N_];   // 384 MB  [b][3C][N]
__device__ float g_hv [(size_t)B_ * C_ * N_];       // 128 MB  [b][C][N]
__device__ float g_scale[B_ * C_];
__device__ float g_shift[B_ * C_];

// ---------------------------------------------------------------------------
// Kernel 1: group-norm statistics -> per (b,c) affine scale/shift
// ---------------------------------------------------------------------------
__global__ __launch_bounds__(256) void gn_stats_kernel(
    const float* __restrict__ x,
    const float* __restrict__ gamma,
    const float* __restrict__ beta)
{
    int bg = blockIdx.x;
    int b = bg / NG_, g = bg % NG_;
    const float4* xp = (const float4*)(x + ((size_t)b * C_ + (size_t)g * CPG_) * N_);
    const int total4 = CPG_ * N_ / 4;

    float s = 0.f, ss = 0.f;
    for (int i = threadIdx.x; i < total4; i += 256) {
        float4 v = xp[i];
        s  += v.x + v.y + v.z + v.w;
        ss += v.x*v.x + v.y*v.y + v.z*v.z + v.w*v.w;
    }
    __shared__ float sh_s[256], sh_q[256];
    sh_s[threadIdx.x] = s; sh_q[threadIdx.x] = ss;
    __syncthreads();
    for (int off = 128; off > 0; off >>= 1) {
        if (threadIdx.x < off) {
            sh_s[threadIdx.x] += sh_s[threadIdx.x + off];
            sh_q[threadIdx.x] += sh_q[threadIdx.x + off];
        }
        __syncthreads();
    }
    float inv_n = 1.f / (float)(CPG_ * N_);
    float mean = sh_s[0] * inv_n;
    float var  = sh_q[0] * inv_n - mean * mean;
    float rstd = rsqrtf(var + EPS_);
    if (threadIdx.x < CPG_) {
        int c = g * CPG_ + threadIdx.x;
        float ga = gamma[c];
        g_scale[b * C_ + c] = rstd * ga;
        g_shift[b * C_ + c] = beta[c] - mean * rstd * ga;
    }
}

// ---------------------------------------------------------------------------
// tf32 helpers
// ---------------------------------------------------------------------------
__device__ __forceinline__ float to_tf32(float x) {
    uint32_t u;
    asm("cvt.rna.tf32.f32 %0, %1;" : "=r"(u) : "f"(x));
    return __uint_as_float(u);
}

__device__ __forceinline__ void mma8(float c[4],
                                     float a0, float a1, float a2, float a3,
                                     float b0, float b1)
{
    asm volatile(
        "mma.sync.aligned.m16n8k8.row.col.f32.tf32.tf32.f32 "
        "{%0,%1,%2,%3}, {%4,%5,%6,%7}, {%8,%9}, {%0,%1,%2,%3};\n"
        : "+f"(c[0]), "+f"(c[1]), "+f"(c[2]), "+f"(c[3])
        : "r"(__float_as_uint(a0)), "r"(__float_as_uint(a1)),
          "r"(__float_as_uint(a2)), "r"(__float_as_uint(a3)),
          "r"(__float_as_uint(b0)), "r"(__float_as_uint(b1)));
}

// ---------------------------------------------------------------------------
// tf32 GEMM: 128x128 tile, BK=32, 8 warps of 64x32, double-buffered smem
// MODE 0: qkv — B = groupnorm(x), Out = g_qkv, +bias
// MODE 1: out — B = g_hv, Out = param, +bias +x residual
// ---------------------------------------------------------------------------
template<int MODE>
__global__ __launch_bounds__(256, 1) void gemm_tc(
    const float* __restrict__ W,
    const float* __restrict__ Bsrc_x,
    const float* __restrict__ bias,
    const float* __restrict__ resid,
    float* __restrict__ Out)
{
    int b  = blockIdx.z;
    int bm = blockIdx.y;
    int bn = blockIdx.x;

    __shared__ float As[2][128][36];    // [m][k], stride 36 -> 4*gid+tig banks
    __shared__ float Bs[2][32][136];    // [k][n], stride 136 -> 8*tig+gid banks

    const float* Bb = (MODE == 0) ? (Bsrc_x + (size_t)b * C_ * N_)
                                  : (g_hv   + (size_t)b * C_ * N_);
    const float* scl = g_scale + b * C_;
    const float* shf = g_shift + b * C_;

    int tid  = threadIdx.x;
    int lane = tid & 31;
    int wid  = tid >> 5;
    int gid  = lane >> 2;
    int tig  = lane & 3;
    int m_warp = (wid >> 2) * 64;
    int n_warp = (wid & 3) * 32;

    float acc[4][4][4];
    #pragma unroll
    for (int mt = 0; mt < 4; mt++)
        #pragma unroll
        for (int nt = 0; nt < 4; nt++)
            #pragma unroll
            for (int r = 0; r < 4; r++) acc[mt][nt][r] = 0.f;

    float4 ra[4], rb[4];

    // prefetch k0 = 0
    #pragma unroll
    for (int l = 0; l < 4; l++) {
        int idx = tid + l * 256;
        int m = idx >> 3, k4 = idx & 7;
        ra[l] = *(const float4*)(W + (size_t)(bm * 128 + m) * C_ + k4 * 4);
    }
    #pragma unroll
    for (int l = 0; l < 4; l++) {
        int idx = tid + l * 256;
        int k = idx >> 5, n4 = idx & 31;
        rb[l] = *(const float4*)(Bb + (size_t)k * N_ + bn * 128 + n4 * 4);
    }

    int buf = 0;
    for (int k0 = 0; k0 < C_; k0 += 32) {
        // stage current tile (tf32 convert; MODE 0 applies groupnorm affine)
        #pragma unroll
        for (int l = 0; l < 4; l++) {
            int idx = tid + l * 256;
            int m = idx >> 3, k4 = idx & 7;
            float4 v = ra[l];
            *(float4*)&As[buf][m][k4 * 4] =
                make_float4(to_tf32(v.x), to_tf32(v.y), to_tf32(v.z), to_tf32(v.w));
        }
        #pragma unroll
        for (int l = 0; l < 4; l++) {
            int idx = tid + l * 256;
            int k = idx >> 5, n4 = idx & 31;
            float4 v = rb[l];
            if (MODE == 0) {
                float sc = scl[k0 + k], sf = shf[k0 + k];
                v.x = v.x * sc + sf; v.y = v.y * sc + sf;
                v.z = v.z * sc + sf; v.w = v.w * sc + sf;
            }
            *(float4*)&Bs[buf][k][n4 * 4] =
                make_float4(to_tf32(v.x), to_tf32(v.y), to_tf32(v.z), to_tf32(v.w));
        }
        __syncthreads();

        // prefetch next tile (overlaps with mma chain below)
        if (k0 + 32 < C_) {
            #pragma unroll
            for (int l = 0; l < 4; l++) {
                int idx = tid + l * 256;
                int m = idx >> 3, k4 = idx & 7;
                ra[l] = *(const float4*)(W + (size_t)(bm * 128 + m) * C_ + k0 + 32 + k4 * 4);
            }
            #pragma unroll
            for (int l = 0; l < 4; l++) {
                int idx = tid + l * 256;
                int k = idx >> 5, n4 = idx & 31;
                rb[l] = *(const float4*)(Bb + (size_t)(k0 + 32 + k) * N_ + bn * 128 + n4 * 4);
            }
        }

        #pragma unroll
        for (int ks = 0; ks < 4; ks++) {
            int kb = ks * 8;
            float af[4][4], bf[4][2];
            #pragma unroll
            for (int mt = 0; mt < 4; mt++) {
                int m0 = m_warp + mt * 16 + gid;
                af[mt][0] = As[buf][m0][kb + tig];
                af[mt][1] = As[buf][m0 + 8][kb + tig];
                af[mt][2] = As[buf][m0][kb + tig + 4];
                af[mt][3] = As[buf][m0 + 8][kb + tig + 4];
            }
            #pragma unroll
            for (int nt = 0; nt < 4; nt++) {
                int n0 = n_warp + nt * 8 + gid;
                bf[nt][0] = Bs[buf][kb + tig][n0];
                bf[nt][1] = Bs[buf][kb + tig + 4][n0];
            }
            #pragma unroll
            for (int mt = 0; mt < 4; mt++)
                #pragma unroll
                for (int nt = 0; nt < 4; nt++)
                    mma8(acc[mt][nt], af[mt][0], af[mt][1], af[mt][2], af[mt][3],
                         bf[nt][0], bf[nt][1]);
        }
        buf ^= 1;
    }

    // epilogue
    #pragma unroll
    for (int mt = 0; mt < 4; mt++) {
        int r0  = m_warp + mt * 16 + gid;
        int gr0 = bm * 128 + r0;
        float bi0 = bias[gr0];
        float bi1 = bias[gr0 + 8];
        #pragma unroll
        for (int nt = 0; nt < 4; nt++) {
            int col = n_warp + nt * 8 + tig * 2;
            if (MODE == 0) {
                float* o = g_qkv + ((size_t)b * 3 * C_ + gr0) * N_ + bn * 128 + col;
                *(float2*)o            = make_float2(acc[mt][nt][0] + bi0, acc[mt][nt][1] + bi0);
                *(float2*)(o + 8 * N_) = make_float2(acc[mt][nt][2] + bi1, acc[mt][nt][3] + bi1);
            } else {
                size_t base = ((size_t)b * C_ + gr0) * N_ + bn * 128 + col;
                float2 x0 = *(const float2*)(resid + base);
                float2 x1 = *(const float2*)(resid + base + 8 * N_);
                *(float2*)(Out + base) =
                    make_float2(acc[mt][nt][0] + bi0 + x0.x, acc[mt][nt][1] + bi0 + x0.y);
                *(float2*)(Out + base + 8 * N_) =
                    make_float2(acc[mt][nt][2] + bi1 + x1.x, acc[mt][nt][3] + bi1 + x1.y);
            }
        }
    }
}

// ---------------------------------------------------------------------------
// Kernel 3: tensor-core attention per (b,h).
// Phase A: S[64x64] = q·k^T over N=4096 (mma tf32, K-tiles of 64)
// Softmax rows. Phase C: hv = P·v streamed over N (n-chunks of 64).
// smem: region0 (4608 f): q tile (stride 68) -> S (stride 68) -> v (stride 72)
//       region1 (4352 f): k tile (stride 68) -> P (stride 68)
// ---------------------------------------------------------------------------
#define SQ_S 68
#define SV_S 72

__global__ __launch_bounds__(256) void attn_kernel()
{
    __shared__ float sm[64 * SV_S + 64 * SQ_S];
    float* r0 = sm;                 // q / S / v
    float* r1 = sm + 64 * SV_S;     // k / P

    int bh = blockIdx.x;
    int b = bh / NH_, h = bh % NH_;
    const float* q = g_qkv + ((size_t)b * 3 * C_ + 0 * C_ + (size_t)h * HD_) * N_;
    const float* k = g_qkv + ((size_t)b * 3 * C_ + 1 * C_ + (size_t)h * HD_) * N_;
    const float* v = g_qkv + ((size_t)b * 3 * C_ + 2 * C_ + (size_t)h * HD_) * N_;
    float* hv = g_hv + ((size_t)b * C_ + (size_t)h * HD_) * N_;

    int tid  = threadIdx.x;
    int lane = tid & 31;
    int wid  = tid >> 5;
    int gid  = lane >> 2;
    int tig  = lane & 3;
    int m_warp = (wid & 3) * 16;    // 0,16,32,48
    int n_warp = (wid >> 2) * 32;   // 0,32

    // ---------------- Phase A: S = q k^T ----------------
    float acc[4][4];
    #pragma unroll
    for (int nt = 0; nt < 4; nt++)
        #pragma unroll
        for (int r = 0; r < 4; r++) acc[nt][r] = 0.f;

    float4 rq[4], rk[4];
    #pragma unroll
    for (int l = 0; l < 4; l++) {
        int idx = tid + l * 256;
        int row = idx >> 4, c4 = idx & 15;
        rq[l] = *(const float4*)(q + (size_t)row * N_ + c4 * 4);
        rk[l] = *(const float4*)(k + (size_t)row * N_ + c4 * 4);
    }

    for (int n0 = 0; n0 < N_; n0 += 64) {
        #pragma unroll
        for (int l = 0; l < 4; l++) {
            int idx = tid + l * 256;
            int row = idx >> 4, c4 = idx & 15;
            float4 a = rq[l], bb = rk[l];
            *(float4*)(r0 + row * SQ_S + c4 * 4) =
                make_float4(to_tf32(a.x), to_tf32(a.y), to_tf32(a.z), to_tf32(a.w));
            *(float4*)(r1 + row * SQ_S + c4 * 4) =
                make_float4(to_tf32(bb.x), to_tf32(bb.y), to_tf32(bb.z), to_tf32(bb.w));
        }
        __syncthreads();
        if (n0 + 64 < N_) {
            #pragma unroll
            for (int l = 0; l < 4; l++) {
                int idx = tid + l * 256;
                int row = idx >> 4, c4 = idx & 15;
                rq[l] = *(const float4*)(q + (size_t)row * N_ + n0 + 64 + c4 * 4);
                rk[l] = *(const float4*)(k + (size_t)row * N_ + n0 + 64 + c4 * 4);
            }
        }
        #pragma unroll
        for (int ks = 0; ks < 8; ks++) {
            int kb = ks * 8;
            float a0 = r0[(m_warp + gid) * SQ_S + kb + tig];
            float a1 = r0[(m_warp + gid + 8) * SQ_S + kb + tig];
            float a2 = r0[(m_warp + gid) * SQ_S + kb + tig + 4];
            float a3 = r0[(m_warp + gid + 8) * SQ_S + kb + tig + 4];
            float bf[4][2];
            #pragma unroll
            for (int nt = 0; nt < 4; nt++) {
                int e0 = n_warp + nt * 8 + gid;
                bf[nt][0] = r1[e0 * SQ_S + kb + tig];
                bf[nt][1] = r1[e0 * SQ_S + kb + tig + 4];
            }
            #pragma unroll
            for (int nt = 0; nt < 4; nt++)
                mma8(acc[nt], a0, a1, a2, a3, bf[nt][0], bf[nt][1]);
        }
        __syncthreads();
    }

    // write scaled S into r0 (q done)
    const float scale = 0.125f;
    #pragma unroll
    for (int nt = 0; nt < 4; nt++) {
        int col = n_warp + nt * 8 + tig * 2;
        int rA = m_warp + gid;
        r0[rA * SQ_S + col]           = acc[nt][0] * scale;
        r0[rA * SQ_S + col + 1]       = acc[nt][1] * scale;
        r0[(rA + 8) * SQ_S + col]     = acc[nt][2] * scale;
        r0[(rA + 8) * SQ_S + col + 1] = acc[nt][3] * scale;
    }
    __syncthreads();

    // softmax rows -> P (tf32) into r1 (k done)
    if (tid < 64) {
        int r = tid;
        float m = -1e30f;
        for (int c = 0; c < 64; c++) m = fmaxf(m, r0[r * SQ_S + c]);
        float s = 0.f;
        float e[64];
        #pragma unroll 8
        for (int c = 0; c < 64; c++) {
            e[c] = __expf(r0[r * SQ_S + c] - m);
            s += e[c];
        }
        float inv = 1.f / s;
        #pragma unroll 8
        for (int c = 0; c < 64; c++)
            r1[r * SQ_S + c] = to_tf32(e[c] * inv);
    }
    __syncthreads();

    // ---------------- Phase C: hv = P v ----------------
    float4 rv[4];
    #pragma unroll
    for (int l = 0; l < 4; l++) {
        int idx = tid + l * 256;
        int row = idx >> 4, c4 = idx & 15;
        rv[l] = *(const float4*)(v + (size_t)row * N_ + c4 * 4);
    }

    for (int n0 = 0; n0 < N_; n0 += 64) {
        #pragma unroll
        for (int l = 0; l < 4; l++) {
            int idx = tid + l * 256;
            int row = idx >> 4, c4 = idx & 15;
            float4 vv = rv[l];
            *(float4*)(r0 + row * SV_S + c4 * 4) =
                make_float4(to_tf32(vv.x), to_tf32(vv.y), to_tf32(vv.z), to_tf32(vv.w));
        }
        __syncthreads();
        if (n0 + 64 < N_) {
            #pragma unroll
            for (int l = 0; l < 4; l++) {
                int idx = tid + l * 256;
                int row = idx >> 4, c4 = idx & 15;
                rv[l] = *(const float4*)(v + (size_t)row * N_ + n0 + 64 + c4 * 4);
            }
        }
        float a2[4][4];
        #pragma unroll
        for (int nt = 0; nt < 4; nt++)
            #pragma unroll
            for (int r = 0; r < 4; r++) a2[nt][r] = 0.f;

        #pragma unroll
        for (int ks = 0; ks < 8; ks++) {
            int kb = ks * 8;
            float a0 = r1[(m_warp + gid) * SQ_S + kb + tig];
            float a1 = r1[(m_warp + gid + 8) * SQ_S + kb + tig];
            float a2f = r1[(m_warp + gid) * SQ_S + kb + tig + 4];
            float a3 = r1[(m_warp + gid + 8) * SQ_S + kb + tig + 4];
            float bf[4][2];
            #pragma unroll
            for (int nt = 0; nt < 4; nt++) {
                int nn = n_warp + nt * 8 + gid;
                bf[nt][0] = r0[(kb + tig) * SV_S + nn];
                bf[nt][1] = r0[(kb + tig + 4) * SV_S + nn];
            }
            #pragma unroll
            for (int nt = 0; nt < 4; nt++)
                mma8(a2[nt], a0, a1, a2f, a3, bf[nt][0], bf[nt][1]);
        }
        #pragma unroll
        for (int nt = 0; nt < 4; nt++) {
            int col = n0 + n_warp + nt * 8 + tig * 2;
            int rA = m_warp + gid;
            *(float2*)(hv + (size_t)rA * N_ + col)       = make_float2(a2[nt][0], a2[nt][1]);
            *(float2*)(hv + (size_t)(rA + 8) * N_ + col) = make_float2(a2[nt][2], a2[nt][3]);
        }
        __syncthreads();
    }
}

// ---------------------------------------------------------------------------
extern "C" void kernel_launch(void* const* d_in, const int* in_sizes, int n_in,
                              void* d_out, int out_size)
{
    const float* x     = (const float*)d_in[0];
    const float* gamma = (const float*)d_in[1];
    const float* beta  = (const float*)d_in[2];
    const float* w_qkv = (const float*)d_in[3];
    const float* b_qkv = (const float*)d_in[4];
    const float* w_out = (const float*)d_in[5];
    const float* b_out = (const float*)d_in[6];
    float* out = (float*)d_out;

    gn_stats_kernel<<<B_ * NG_, 256>>>(x, gamma, beta);
    gemm_tc<0><<<dim3(N_ / 128, (3 * C_) / 128, B_), 256>>>(w_qkv, x, b_qkv, nullptr, nullptr);
    attn_kernel<<<B_ * NH_, 256>>>();
    gemm_tc<1><<<dim3(N_ / 128, C_ / 128, B_), 256>>>(w_out, nullptr, b_out, x, out);
}

// round 4
// speedup vs baseline: 3.3527x; 1.2377x over previous
#include <cuda_runtime.h>
#include <math.h>
#include <stdint.h>

#define B_   16
#define C_   512
#define N_   4096
#define NH_  8
#define HD_  64
#define NG_  8
#define CPG_ 64
#define EPS_ 1e-5f

// Scratch (allocation-free rule: static device globals)
__device__ float g_qkv[(size_t)B_ * 3 * C_ * N_];    // 384 MB, tf32-rounded
__device__ float g_hv [(size_t)B_ * C_ * N_];        // 128 MB, tf32-rounded
__device__ float g_h32[(size_t)B_ * C_ * N_];        // 128 MB, tf32(groupnorm(x))
__device__ float g_wq32[3 * C_ * C_];                // tf32 w_qkv
__device__ float g_wo32[C_ * C_];                    // tf32 w_out

// ---------------------------------------------------------------------------
// tf32 / mma / cp.async helpers
// ---------------------------------------------------------------------------
__device__ __forceinline__ float to_tf32(float x) {
    uint32_t u;
    asm("cvt.rna.tf32.f32 %0, %1;" : "=r"(u) : "f"(x));
    return __uint_as_float(u);
}

__device__ __forceinline__ void mma8(float c[4],
                                     float a0, float a1, float a2, float a3,
                                     float b0, float b1)
{
    asm volatile(
        "mma.sync.aligned.m16n8k8.row.col.f32.tf32.tf32.f32 "
        "{%0,%1,%2,%3}, {%4,%5,%6,%7}, {%8,%9}, {%0,%1,%2,%3};\n"
        : "+f"(c[0]), "+f"(c[1]), "+f"(c[2]), "+f"(c[3])
        : "r"(__float_as_uint(a0)), "r"(__float_as_uint(a1)),
          "r"(__float_as_uint(a2)), "r"(__float_as_uint(a3)),
          "r"(__float_as_uint(b0)), "r"(__float_as_uint(b1)));
}

__device__ __forceinline__ void cp16(uint32_t dst, const void* src) {
    asm volatile("cp.async.cg.shared.global [%0], [%1], 16;\n"
                 :: "r"(dst), "l"(src));
}
__device__ __forceinline__ void cp_commit() {
    asm volatile("cp.async.commit_group;\n" ::: "memory");
}
__device__ __forceinline__ void cp_wait0() {
    asm volatile("cp.async.wait_group 0;\n" ::: "memory");
}

// ---------------------------------------------------------------------------
// Kernel 0: convert weights to tf32 scratch
// ---------------------------------------------------------------------------
__global__ __launch_bounds__(256) void cvt_w_kernel(
    const float* __restrict__ wq, const float* __restrict__ wo)
{
    int i = blockIdx.x * 256 + threadIdx.x;
    if (i < 3 * C_ * C_) g_wq32[i] = to_tf32(wq[i]);
    if (i < C_ * C_)     g_wo32[i] = to_tf32(wo[i]);
}

// ---------------------------------------------------------------------------
// Kernel 1: group-norm stats + write h32 = tf32(x * scale + shift)
// grid = B*NG, 256 threads
// ---------------------------------------------------------------------------
__global__ __launch_bounds__(256) void gn_kernel(
    const float* __restrict__ x,
    const float* __restrict__ gamma,
    const float* __restrict__ beta)
{
    int bg = blockIdx.x;
    int b = bg / NG_, g = bg % NG_;
    const float4* xp = (const float4*)(x + ((size_t)b * C_ + (size_t)g * CPG_) * N_);
    const int total4 = CPG_ * N_ / 4;

    float s = 0.f, ss = 0.f;
    for (int i = threadIdx.x; i < total4; i += 256) {
        float4 v = xp[i];
        s  += v.x + v.y + v.z + v.w;
        ss += v.x*v.x + v.y*v.y + v.z*v.z + v.w*v.w;
    }
    __shared__ float sh_s[256], sh_q[256];
    __shared__ float s_sc[CPG_], s_sf[CPG_];
    sh_s[threadIdx.x] = s; sh_q[threadIdx.x] = ss;
    __syncthreads();
    for (int off = 128; off > 0; off >>= 1) {
        if (threadIdx.x < off) {
            sh_s[threadIdx.x] += sh_s[threadIdx.x + off];
            sh_q[threadIdx.x] += sh_q[threadIdx.x + off];
        }
        __syncthreads();
    }
    float inv_n = 1.f / (float)(CPG_ * N_);
    float mean = sh_s[0] * inv_n;
    float var  = sh_q[0] * inv_n - mean * mean;
    float rstd = rsqrtf(var + EPS_);
    if (threadIdx.x < CPG_) {
        int c = g * CPG_ + threadIdx.x;
        float ga = gamma[c];
        s_sc[threadIdx.x] = rstd * ga;
        s_sf[threadIdx.x] = beta[c] - mean * rstd * ga;
    }
    __syncthreads();

    float4* hp = (float4*)(g_h32 + ((size_t)b * C_ + (size_t)g * CPG_) * N_);
    const int q4 = N_ / 4;   // float4 per channel
    for (int i = threadIdx.x; i < total4; i += 256) {
        int ch = i / q4;
        float sc = s_sc[ch], sf = s_sf[ch];
        float4 v = xp[i];
        hp[i] = make_float4(to_tf32(v.x*sc+sf), to_tf32(v.y*sc+sf),
                            to_tf32(v.z*sc+sf), to_tf32(v.w*sc+sf));
    }
}

// ---------------------------------------------------------------------------
// tf32 GEMM: 128x128 tile, BK=32, 8 warps of 64x32, cp.async double buffer,
// 2 CTAs/SM. Operands are pre-converted tf32.
// MODE 0: Out = g_qkv (tf32-rounded), +bias
// MODE 1: Out = param, +bias +x residual
// ---------------------------------------------------------------------------
template<int MODE>
__global__ __launch_bounds__(256, 2) void gemm_tc(
    const float* __restrict__ W,       // tf32 [M][C]
    const float* __restrict__ Bmat,    // tf32 [B][C][N]
    const float* __restrict__ bias,
    const float* __restrict__ resid,
    float* __restrict__ Out)
{
    int b  = blockIdx.z;
    int bm = blockIdx.y;
    int bn = blockIdx.x;

    __shared__ __align__(16) float As[2][128][36];    // [m][k], conflict-free frags
    __shared__ __align__(16) float Bs[2][32][136];    // [k][n], conflict-free frags

    const float* Bb = Bmat + (size_t)b * C_ * N_;
    const float* Wb = W + (size_t)bm * 128 * C_;

    int tid  = threadIdx.x;
    int lane = tid & 31;
    int wid  = tid >> 5;
    int gid  = lane >> 2;
    int tig  = lane & 3;
    int m_warp = (wid >> 2) * 64;
    int n_warp = (wid & 3) * 32;

    uint32_t As_base = (uint32_t)__cvta_generic_to_shared(&As[0][0][0]);
    uint32_t Bs_base = (uint32_t)__cvta_generic_to_shared(&Bs[0][0][0]);

    // per-thread fixed load slots
    int am = tid >> 3, ak4 = tid & 7;            // A: 2 rows per thread (am, am+... no: l loop)
    int bk = tid >> 5, bn4 = tid & 31;

    float acc[4][4][4];
    #pragma unroll
    for (int mt = 0; mt < 4; mt++)
        #pragma unroll
        for (int nt = 0; nt < 4; nt++)
            #pragma unroll
            for (int r = 0; r < 4; r++) acc[mt][nt][r] = 0.f;

    // issue tile k0 into stage s
    auto issue = [&](int k0, int s) {
        #pragma unroll
        for (int l = 0; l < 4; l++) {
            int m = am + l * 32;
            cp16(As_base + (((s * 128 + m) * 36) + ak4 * 4) * 4,
                 Wb + (size_t)m * C_ + k0 + ak4 * 4);
        }
        #pragma unroll
        for (int l = 0; l < 4; l++) {
            int k = bk + l * 8;
            cp16(Bs_base + (((s * 32 + k) * 136) + bn4 * 4) * 4,
                 Bb + (size_t)(k0 + k) * N_ + bn * 128 + bn4 * 4);
        }
        cp_commit();
    };

    issue(0, 0);
    int buf = 0;
    for (int k0 = 0; k0 < C_; k0 += 32) {
        cp_wait0();
        __syncthreads();
        if (k0 + 32 < C_) issue(k0 + 32, buf ^ 1);

        #pragma unroll
        for (int ks = 0; ks < 4; ks++) {
            int kb = ks * 8;
            float af[4][4], bf[4][2];
            #pragma unroll
            for (int mt = 0; mt < 4; mt++) {
                int m0 = m_warp + mt * 16 + gid;
                af[mt][0] = As[buf][m0][kb + tig];
                af[mt][1] = As[buf][m0 + 8][kb + tig];
                af[mt][2] = As[buf][m0][kb + tig + 4];
                af[mt][3] = As[buf][m0 + 8][kb + tig + 4];
            }
            #pragma unroll
            for (int nt = 0; nt < 4; nt++) {
                int n0 = n_warp + nt * 8 + gid;
                bf[nt][0] = Bs[buf][kb + tig][n0];
                bf[nt][1] = Bs[buf][kb + tig + 4][n0];
            }
            #pragma unroll
            for (int mt = 0; mt < 4; mt++)
                #pragma unroll
                for (int nt = 0; nt < 4; nt++)
                    mma8(acc[mt][nt], af[mt][0], af[mt][1], af[mt][2], af[mt][3],
                         bf[nt][0], bf[nt][1]);
        }
        buf ^= 1;
    }

    // epilogue
    #pragma unroll
    for (int mt = 0; mt < 4; mt++) {
        int r0  = m_warp + mt * 16 + gid;
        int gr0 = bm * 128 + r0;
        float bi0 = bias[gr0];
        float bi1 = bias[gr0 + 8];
        #pragma unroll
        for (int nt = 0; nt < 4; nt++) {
            int col = n_warp + nt * 8 + tig * 2;
            if (MODE == 0) {
                float* o = g_qkv + ((size_t)b * 3 * C_ + gr0) * N_ + bn * 128 + col;
                *(float2*)o =
                    make_float2(to_tf32(acc[mt][nt][0] + bi0), to_tf32(acc[mt][nt][1] + bi0));
                *(float2*)(o + 8 * N_) =
                    make_float2(to_tf32(acc[mt][nt][2] + bi1), to_tf32(acc[mt][nt][3] + bi1));
            } else {
                size_t base = ((size_t)b * C_ + gr0) * N_ + bn * 128 + col;
                float2 x0 = *(const float2*)(resid + base);
                float2 x1 = *(const float2*)(resid + base + 8 * N_);
                *(float2*)(Out + base) =
                    make_float2(acc[mt][nt][0] + bi0 + x0.x, acc[mt][nt][1] + bi0 + x0.y);
                *(float2*)(Out + base + 8 * N_) =
                    make_float2(acc[mt][nt][2] + bi1 + x1.x, acc[mt][nt][3] + bi1 + x1.y);
            }
        }
    }
}

// ---------------------------------------------------------------------------
// Kernel 3: tensor-core attention per (b,h). Inputs in g_qkv pre-rounded tf32.
// ---------------------------------------------------------------------------
#define SQ_S 68
#define SV_S 72

__global__ __launch_bounds__(256) void attn_kernel()
{
    __shared__ float sm[64 * SV_S + 64 * SQ_S];
    float* r0 = sm;                 // q / S / v
    float* r1 = sm + 64 * SV_S;     // k / P

    int bh = blockIdx.x;
    int b = bh / NH_, h = bh % NH_;
    const float* q = g_qkv + ((size_t)b * 3 * C_ + 0 * C_ + (size_t)h * HD_) * N_;
    const float* k = g_qkv + ((size_t)b * 3 * C_ + 1 * C_ + (size_t)h * HD_) * N_;
    const float* v = g_qkv + ((size_t)b * 3 * C_ + 2 * C_ + (size_t)h * HD_) * N_;
    float* hv = g_hv + ((size_t)b * C_ + (size_t)h * HD_) * N_;

    int tid  = threadIdx.x;
    int lane = tid & 31;
    int wid  = tid >> 5;
    int gid  = lane >> 2;
    int tig  = lane & 3;
    int m_warp = (wid & 3) * 16;
    int n_warp = (wid >> 2) * 32;

    // ---------------- Phase A: S = q k^T ----------------
    float acc[4][4];
    #pragma unroll
    for (int nt = 0; nt < 4; nt++)
        #pragma unroll
        for (int r = 0; r < 4; r++) acc[nt][r] = 0.f;

    float4 rq[4], rk[4];
    #pragma unroll
    for (int l = 0; l < 4; l++) {
        int idx = tid + l * 256;
        int row = idx >> 4, c4 = idx & 15;
        rq[l] = *(const float4*)(q + (size_t)row * N_ + c4 * 4);
        rk[l] = *(const float4*)(k + (size_t)row * N_ + c4 * 4);
    }

    for (int n0 = 0; n0 < N_; n0 += 64) {
        #pragma unroll
        for (int l = 0; l < 4; l++) {
            int idx = tid + l * 256;
            int row = idx >> 4, c4 = idx & 15;
            *(float4*)(r0 + row * SQ_S + c4 * 4) = rq[l];
            *(float4*)(r1 + row * SQ_S + c4 * 4) = rk[l];
        }
        __syncthreads();
        if (n0 + 64 < N_) {
            #pragma unroll
            for (int l = 0; l < 4; l++) {
                int idx = tid + l * 256;
                int row = idx >> 4, c4 = idx & 15;
                rq[l] = *(const float4*)(q + (size_t)row * N_ + n0 + 64 + c4 * 4);
                rk[l] = *(const float4*)(k + (size_t)row * N_ + n0 + 64 + c4 * 4);
            }
        }
        #pragma unroll
        for (int ks = 0; ks < 8; ks++) {
            int kb = ks * 8;
            float a0 = r0[(m_warp + gid) * SQ_S + kb + tig];
            float a1 = r0[(m_warp + gid + 8) * SQ_S + kb + tig];
            float a2 = r0[(m_warp + gid) * SQ_S + kb + tig + 4];
            float a3 = r0[(m_warp + gid + 8) * SQ_S + kb + tig + 4];
            float bf[4][2];
            #pragma unroll
            for (int nt = 0; nt < 4; nt++) {
                int e0 = n_warp + nt * 8 + gid;
                bf[nt][0] = r1[e0 * SQ_S + kb + tig];
                bf[nt][1] = r1[e0 * SQ_S + kb + tig + 4];
            }
            #pragma unroll
            for (int nt = 0; nt < 4; nt++)
                mma8(acc[nt], a0, a1, a2, a3, bf[nt][0], bf[nt][1]);
        }
        __syncthreads();
    }

    const float scale = 0.125f;
    #pragma unroll
    for (int nt = 0; nt < 4; nt++) {
        int col = n_warp + nt * 8 + tig * 2;
        int rA = m_warp + gid;
        r0[rA * SQ_S + col]           = acc[nt][0] * scale;
        r0[rA * SQ_S + col + 1]       = acc[nt][1] * scale;
        r0[(rA + 8) * SQ_S + col]     = acc[nt][2] * scale;
        r0[(rA + 8) * SQ_S + col + 1] = acc[nt][3] * scale;
    }
    __syncthreads();

    if (tid < 64) {
        int r = tid;
        float m = -1e30f;
        for (int c = 0; c < 64; c++) m = fmaxf(m, r0[r * SQ_S + c]);
        float s = 0.f;
        float e[64];
        #pragma unroll 8
        for (int c = 0; c < 64; c++) {
            e[c] = __expf(r0[r * SQ_S + c] - m);
            s += e[c];
        }
        float inv = 1.f / s;
        #pragma unroll 8
        for (int c = 0; c < 64; c++)
            r1[r * SQ_S + c] = to_tf32(e[c] * inv);
    }
    __syncthreads();

    // ---------------- Phase C: hv = P v ----------------
    float4 rv[4];
    #pragma unroll
    for (int l = 0; l < 4; l++) {
        int idx = tid + l * 256;
        int row = idx >> 4, c4 = idx & 15;
        rv[l] = *(const float4*)(v + (size_t)row * N_ + c4 * 4);
    }

    for (int n0 = 0; n0 < N_; n0 += 64) {
        #pragma unroll
        for (int l = 0; l < 4; l++) {
            int idx = tid + l * 256;
            int row = idx >> 4, c4 = idx & 15;
            *(float4*)(r0 + row * SV_S + c4 * 4) = rv[l];
        }
        __syncthreads();
        if (n0 + 64 < N_) {
            #pragma unroll
            for (int l = 0; l < 4; l++) {
                int idx = tid + l * 256;
                int row = idx >> 4, c4 = idx & 15;
                rv[l] = *(const float4*)(v + (size_t)row * N_ + n0 + 64 + c4 * 4);
            }
        }
        float a2[4][4];
        #pragma unroll
        for (int nt = 0; nt < 4; nt++)
            #pragma unroll
            for (int r = 0; r < 4; r++) a2[nt][r] = 0.f;

        #pragma unroll
        for (int ks = 0; ks < 8; ks++) {
            int kb = ks * 8;
            float a0 = r1[(m_warp + gid) * SQ_S + kb + tig];
            float a1 = r1[(m_warp + gid + 8) * SQ_S + kb + tig];
            float a2f = r1[(m_warp + gid) * SQ_S + kb + tig + 4];
            float a3 = r1[(m_warp + gid + 8) * SQ_S + kb + tig + 4];
            float bf[4][2];
            #pragma unroll
            for (int nt = 0; nt < 4; nt++) {
                int nn = n_warp + nt * 8 + gid;
                bf[nt][0] = r0[(kb + tig) * SV_S + nn];
                bf[nt][1] = r0[(kb + tig + 4) * SV_S + nn];
            }
            #pragma unroll
            for (int nt = 0; nt < 4; nt++)
                mma8(a2[nt], a0, a1, a2f, a3, bf[nt][0], bf[nt][1]);
        }
        #pragma unroll
        for (int nt = 0; nt < 4; nt++) {
            int col = n0 + n_warp + nt * 8 + tig * 2;
            int rA = m_warp + gid;
            *(float2*)(hv + (size_t)rA * N_ + col) =
                make_float2(to_tf32(a2[nt][0]), to_tf32(a2[nt][1]));
            *(float2*)(hv + (size_t)(rA + 8) * N_ + col) =
                make_float2(to_tf32(a2[nt][2]), to_tf32(a2[nt][3]));
        }
        __syncthreads();
    }
}

// ---------------------------------------------------------------------------
extern "C" void kernel_launch(void* const* d_in, const int* in_sizes, int n_in,
                              void* d_out, int out_size)
{
    const float* x     = (const float*)d_in[0];
    const float* gamma = (const float*)d_in[1];
    const float* beta  = (const float*)d_in[2];
    const float* w_qkv = (const float*)d_in[3];
    const float* b_qkv = (const float*)d_in[4];
    const float* w_out = (const float*)d_in[5];
    const float* b_out = (const float*)d_in[6];
    float* out = (float*)d_out;

    float* wq32;  cudaGetSymbolAddress((void**)&wq32, g_wq32);
    float* wo32;  cudaGetSymbolAddress((void**)&wo32, g_wo32);
    float* h32;   cudaGetSymbolAddress((void**)&h32,  g_h32);
    float* hv;    cudaGetSymbolAddress((void**)&hv,   g_hv);

    cvt_w_kernel<<<(3 * C_ * C_) / 256, 256>>>(w_qkv, w_out);
    gn_kernel<<<B_ * NG_, 256>>>(x, gamma, beta);
    gemm_tc<0><<<dim3(N_ / 128, (3 * C_) / 128, B_), 256>>>(wq32, h32, b_qkv, nullptr, nullptr);
    attn_kernel<<<B_ * NH_, 256>>>();
    gemm_tc<1><<<dim3(N_ / 128, C_ / 128, B_), 256>>>(wo32, hv, b_out, x, out);
}

// round 5
// speedup vs baseline: 3.7926x; 1.1312x over previous
#include <cuda_runtime.h>
#include <math.h>
#include <stdint.h>

#define B_   16
#define C_   512
#define N_   4096
#define NH_  8
#define HD_  64
#define NG_  8
#define CPG_ 64
#define EPS_ 1e-5f
#define KT_  (C_ / 8)        // 64 k-tiles of 8
#define NCH_ 8               // attention N-chunks
#define NCW_ (N_ / NCH_)     // 512 per chunk

// Scratch (allocation-free rule: static device globals)
__device__ float g_qkv[(size_t)B_ * 3 * C_ * N_];    // 384 MB, tf32-rounded
__device__ float g_hv [(size_t)B_ * C_ * N_];        // 128 MB, tf32-rounded
__device__ float g_h32[(size_t)B_ * C_ * N_];        // 128 MB, tf32(groupnorm(x))
__device__ float g_wq32[3 * C_ * C_];                // w_qkv, tf32, fragment-packed
__device__ float g_wo32[C_ * C_];                    // w_out, tf32, fragment-packed
__device__ float g_Sp[(size_t)B_ * NH_ * NCH_ * 64 * 64];  // partial S, 16.8 MB
__device__ float g_P [(size_t)B_ * NH_ * 64 * 64];         // softmax(P), tf32

// ---------------------------------------------------------------------------
// helpers
// ---------------------------------------------------------------------------
__device__ __forceinline__ float to_tf32(float x) {
    uint32_t u;
    asm("cvt.rna.tf32.f32 %0, %1;" : "=r"(u) : "f"(x));
    return __uint_as_float(u);
}

__device__ __forceinline__ void mma8(float c[4],
                                     float a0, float a1, float a2, float a3,
                                     float b0, float b1)
{
    asm volatile(
        "mma.sync.aligned.m16n8k8.row.col.f32.tf32.tf32.f32 "
        "{%0,%1,%2,%3}, {%4,%5,%6,%7}, {%8,%9}, {%0,%1,%2,%3};\n"
        : "+f"(c[0]), "+f"(c[1]), "+f"(c[2]), "+f"(c[3])
        : "r"(__float_as_uint(a0)), "r"(__float_as_uint(a1)),
          "r"(__float_as_uint(a2)), "r"(__float_as_uint(a3)),
          "r"(__float_as_uint(b0)), "r"(__float_as_uint(b1)));
}

__device__ __forceinline__ void cp16(uint32_t dst, const void* src) {
    asm volatile("cp.async.cg.shared.global [%0], [%1], 16;\n"
                 :: "r"(dst), "l"(src));
}
__device__ __forceinline__ void cp_commit() {
    asm volatile("cp.async.commit_group;\n" ::: "memory");
}
__device__ __forceinline__ void cp_wait0() {
    asm volatile("cp.async.wait_group 0;\n" ::: "memory");
}

// ---------------------------------------------------------------------------
// Kernel 0: convert + fragment-pack weights.
// Packed layout: Wp[mt_g][kt_g][lane][a_sel], mt_g=row/16, kt_g=col/8,
// lane = (row%8)*4 + (col%4), a_sel = (row%16>=8) | ((col%8>=4)<<1)
// ---------------------------------------------------------------------------
__device__ __forceinline__ void pack_one(float* dst, const float* src, int i, int M) {
    int row = i / C_, col = i % C_;
    int mt_g = row >> 4, kt_g = col >> 3;
    int row_in = row & 15, k_in = col & 7;
    int lane = (row_in & 7) * 4 + (k_in & 3);
    int a_sel = ((row_in >> 3) & 1) | (((k_in >> 2) & 1) << 1);
    dst[(((size_t)mt_g * KT_ + kt_g) * 32 + lane) * 4 + a_sel] = to_tf32(src[i]);
}

__global__ __launch_bounds__(256) void cvt_w_kernel(
    const float* __restrict__ wq, const float* __restrict__ wo)
{
    int i = blockIdx.x * 256 + threadIdx.x;
    if (i < 3 * C_ * C_) pack_one(g_wq32, wq, i, 3 * C_);
    if (i < C_ * C_)     pack_one(g_wo32, wo, i, C_);
}

// ---------------------------------------------------------------------------
// Kernel 1: group-norm stats + write h32 = tf32(x * scale + shift)
// ---------------------------------------------------------------------------
__global__ __launch_bounds__(256) void gn_kernel(
    const float* __restrict__ x,
    const float* __restrict__ gamma,
    const float* __restrict__ beta)
{
    int bg = blockIdx.x;
    int b = bg / NG_, g = bg % NG_;
    const float4* xp = (const float4*)(x + ((size_t)b * C_ + (size_t)g * CPG_) * N_);
    const int total4 = CPG_ * N_ / 4;

    float s = 0.f, ss = 0.f;
    for (int i = threadIdx.x; i < total4; i += 256) {
        float4 v = xp[i];
        s  += v.x + v.y + v.z + v.w;
        ss += v.x*v.x + v.y*v.y + v.z*v.z + v.w*v.w;
    }
    __shared__ float sh_s[256], sh_q[256];
    __shared__ float s_sc[CPG_], s_sf[CPG_];
    sh_s[threadIdx.x] = s; sh_q[threadIdx.x] = ss;
    __syncthreads();
    for (int off = 128; off > 0; off >>= 1) {
        if (threadIdx.x < off) {
            sh_s[threadIdx.x] += sh_s[threadIdx.x + off];
            sh_q[threadIdx.x] += sh_q[threadIdx.x + off];
        }
        __syncthreads();
    }
    float inv_n = 1.f / (float)(CPG_ * N_);
    float mean = sh_s[0] * inv_n;
    float var  = sh_q[0] * inv_n - mean * mean;
    float rstd = rsqrtf(var + EPS_);
    if (threadIdx.x < CPG_) {
        int c = g * CPG_ + threadIdx.x;
        float ga = gamma[c];
        s_sc[threadIdx.x] = rstd * ga;
        s_sf[threadIdx.x] = beta[c] - mean * rstd * ga;
    }
    __syncthreads();

    float4* hp = (float4*)(g_h32 + ((size_t)b * C_ + (size_t)g * CPG_) * N_);
    const int q4 = N_ / 4;
    for (int i = threadIdx.x; i < total4; i += 256) {
        int ch = i / q4;
        float sc = s_sc[ch], sf = s_sf[ch];
        float4 v = xp[i];
        hp[i] = make_float4(to_tf32(v.x*sc+sf), to_tf32(v.y*sc+sf),
                            to_tf32(v.z*sc+sf), to_tf32(v.w*sc+sf));
    }
}

// ---------------------------------------------------------------------------
// tf32 GEMM: 128x128 tile, BK=32, 8 warps of 64x32, cp.async double buffer,
// fragment-packed A (LDS.128 per m-tile), 2 CTAs/SM.
// ---------------------------------------------------------------------------
template<int MODE>
__global__ __launch_bounds__(256, 2) void gemm_tc(
    const float* __restrict__ Wp,      // packed tf32 [M/16][KT_][32][4]
    const float* __restrict__ Bmat,    // tf32 [B][C][N]
    const float* __restrict__ bias,
    const float* __restrict__ resid,
    float* __restrict__ Out)
{
    int b  = blockIdx.z;
    int bm = blockIdx.y;
    int bn = blockIdx.x;

    __shared__ __align__(16) float AsP[2 * 4096];      // packed A, 32 KB
    __shared__ __align__(16) float Bs[2][32][136];     // [k][n]

    const float* Bb = Bmat + (size_t)b * C_ * N_;

    int tid  = threadIdx.x;
    int lane = tid & 31;
    int wid  = tid >> 5;
    int gid  = lane >> 2;
    int tig  = lane & 3;
    int m_warp = (wid >> 2) * 64;
    int n_warp = (wid & 3) * 32;
    int mt_base = (wid >> 2) * 4;     // packed m-tile base for this warp

    uint32_t AsP_base = (uint32_t)__cvta_generic_to_shared(&AsP[0]);
    uint32_t Bs_base  = (uint32_t)__cvta_generic_to_shared(&Bs[0][0][0]);

    int bk = tid >> 5, bn4 = tid & 31;

    float acc[4][4][4];
    #pragma unroll
    for (int mt = 0; mt < 4; mt++)
        #pragma unroll
        for (int nt = 0; nt < 4; nt++)
            #pragma unroll
            for (int r = 0; r < 4; r++) acc[mt][nt][r] = 0.f;

    auto issue = [&](int k0, int s) {
        int kt0 = k0 >> 3;
        #pragma unroll
        for (int l = 0; l < 4; l++) {
            int f4 = tid + l * 256;          // 0..1023
            int mt = f4 >> 7;                // 0..7
            int rem = f4 & 127;              // float4 within 512-float region
            cp16(AsP_base + (((s * 4096) + mt * 512 + rem * 4)) * 4,
                 Wp + ((size_t)(bm * 8 + mt) * KT_ + kt0) * 128 + rem * 4);
        }
        #pragma unroll
        for (int l = 0; l < 4; l++) {
            int k = bk + l * 8;
            cp16(Bs_base + (((s * 32 + k) * 136) + bn4 * 4) * 4,
                 Bb + (size_t)(k0 + k) * N_ + bn * 128 + bn4 * 4);
        }
        cp_commit();
    };

    issue(0, 0);
    int buf = 0;
    for (int k0 = 0; k0 < C_; k0 += 32) {
        cp_wait0();
        __syncthreads();
        if (k0 + 32 < C_) issue(k0 + 32, buf ^ 1);

        #pragma unroll
        for (int ks = 0; ks < 4; ks++) {
            int kb = ks * 8;
            float4 af[4];
            float bf[4][2];
            #pragma unroll
            for (int mt = 0; mt < 4; mt++)
                af[mt] = *(const float4*)(AsP + buf * 4096 +
                                          ((mt_base + mt) * 4 + ks) * 128 + lane * 4);
            #pragma unroll
            for (int nt = 0; nt < 4; nt++) {
                int n0 = n_warp + nt * 8 + gid;
                bf[nt][0] = Bs[buf][kb + tig][n0];
                bf[nt][1] = Bs[buf][kb + tig + 4][n0];
            }
            #pragma unroll
            for (int mt = 0; mt < 4; mt++)
                #pragma unroll
                for (int nt = 0; nt < 4; nt++)
                    mma8(acc[mt][nt], af[mt].x, af[mt].y, af[mt].z, af[mt].w,
                         bf[nt][0], bf[nt][1]);
        }
        buf ^= 1;
    }

    // epilogue
    #pragma unroll
    for (int mt = 0; mt < 4; mt++) {
        int r0  = m_warp + mt * 16 + gid;
        int gr0 = bm * 128 + r0;
        float bi0 = bias[gr0];
        float bi1 = bias[gr0 + 8];
        #pragma unroll
        for (int nt = 0; nt < 4; nt++) {
            int col = n_warp + nt * 8 + tig * 2;
            if (MODE == 0) {
                float* o = g_qkv + ((size_t)b * 3 * C_ + gr0) * N_ + bn * 128 + col;
                *(float2*)o =
                    make_float2(to_tf32(acc[mt][nt][0] + bi0), to_tf32(acc[mt][nt][1] + bi0));
                *(float2*)(o + 8 * N_) =
                    make_float2(to_tf32(acc[mt][nt][2] + bi1), to_tf32(acc[mt][nt][3] + bi1));
            } else {
                size_t base = ((size_t)b * C_ + gr0) * N_ + bn * 128 + col;
                float2 x0 = *(const float2*)(resid + base);
                float2 x1 = *(const float2*)(resid + base + 8 * N_);
                *(float2*)(Out + base) =
                    make_float2(acc[mt][nt][0] + bi0 + x0.x, acc[mt][nt][1] + bi0 + x0.y);
                *(float2*)(Out + base + 8 * N_) =
                    make_float2(acc[mt][nt][2] + bi1 + x1.x, acc[mt][nt][3] + bi1 + x1.y);
            }
        }
    }
}

// ---------------------------------------------------------------------------
// Attention, split for occupancy. Common warp layout: 8 warps, S-tile 64x64:
// m_warp=(wid&3)*16 rows, n_warp=(wid>>2)*32 cols.
// ---------------------------------------------------------------------------
#define SQ_S 68
#define SV_S 72

// 3a: partial S over one N-chunk. grid (NCH_, B*NH), 256 thr
__global__ __launch_bounds__(256) void attn_qk_kernel()
{
    __shared__ float r0[64 * SQ_S];   // q tiles
    __shared__ float r1[64 * SQ_S];   // k tiles

    int chunk = blockIdx.x;
    int bh = blockIdx.y;
    int b = bh / NH_, h = bh % NH_;
    const float* q = g_qkv + ((size_t)b * 3 * C_ + 0 * C_ + (size_t)h * HD_) * N_ + chunk * NCW_;
    const float* k = g_qkv + ((size_t)b * 3 * C_ + 1 * C_ + (size_t)h * HD_) * N_ + chunk * NCW_;

    int tid  = threadIdx.x;
    int lane = tid & 31;
    int wid  = tid >> 5;
    int gid  = lane >> 2;
    int tig  = lane & 3;
    int m_warp = (wid & 3) * 16;
    int n_warp = (wid >> 2) * 32;

    float acc[4][4];
    #pragma unroll
    for (int nt = 0; nt < 4; nt++)
        #pragma unroll
        for (int r = 0; r < 4; r++) acc[nt][r] = 0.f;

    float4 rq[4], rk[4];
    #pragma unroll
    for (int l = 0; l < 4; l++) {
        int idx = tid + l * 256;
        int row = idx >> 4, c4 = idx & 15;
        rq[l] = *(const float4*)(q + (size_t)row * N_ + c4 * 4);
        rk[l] = *(const float4*)(k + (size_t)row * N_ + c4 * 4);
    }

    for (int n0 = 0; n0 < NCW_; n0 += 64) {
        #pragma unroll
        for (int l = 0; l < 4; l++) {
            int idx = tid + l * 256;
            int row = idx >> 4, c4 = idx & 15;
            *(float4*)(r0 + row * SQ_S + c4 * 4) = rq[l];
            *(float4*)(r1 + row * SQ_S + c4 * 4) = rk[l];
        }
        __syncthreads();
        if (n0 + 64 < NCW_) {
            #pragma unroll
            for (int l = 0; l < 4; l++) {
                int idx = tid + l * 256;
                int row = idx >> 4, c4 = idx & 15;
                rq[l] = *(const float4*)(q + (size_t)row * N_ + n0 + 64 + c4 * 4);
                rk[l] = *(const float4*)(k + (size_t)row * N_ + n0 + 64 + c4 * 4);
            }
        }
        #pragma unroll
        for (int ks = 0; ks < 8; ks++) {
            int kb = ks * 8;
            float a0 = r0[(m_warp + gid) * SQ_S + kb + tig];
            float a1 = r0[(m_warp + gid + 8) * SQ_S + kb + tig];
            float a2 = r0[(m_warp + gid) * SQ_S + kb + tig + 4];
            float a3 = r0[(m_warp + gid + 8) * SQ_S + kb + tig + 4];
            float bf[4][2];
            #pragma unroll
            for (int nt = 0; nt < 4; nt++) {
                int e0 = n_warp + nt * 8 + gid;
                bf[nt][0] = r1[e0 * SQ_S + kb + tig];
                bf[nt][1] = r1[e0 * SQ_S + kb + tig + 4];
            }
            #pragma unroll
            for (int nt = 0; nt < 4; nt++)
                mma8(acc[nt], a0, a1, a2, a3, bf[nt][0], bf[nt][1]);
        }
        __syncthreads();
    }

    float* Sp = g_Sp + ((size_t)bh * NCH_ + chunk) * 64 * 64;
    #pragma unroll
    for (int nt = 0; nt < 4; nt++) {
        int col = n_warp + nt * 8 + tig * 2;
        int rA = m_warp + gid;
        *(float2*)(Sp + rA * 64 + col)       = make_float2(acc[nt][0], acc[nt][1]);
        *(float2*)(Sp + (rA + 8) * 64 + col) = make_float2(acc[nt][2], acc[nt][3]);
    }
}

// 3b: reduce partials + softmax -> P (tf32). grid B*NH, 256 thr
__global__ __launch_bounds__(256) void attn_softmax_kernel()
{
    __shared__ float sS[64 * SQ_S];
    int bh = blockIdx.x;
    int tid = threadIdx.x;
    const float* Sp = g_Sp + (size_t)bh * NCH_ * 64 * 64;
    float* P = g_P + (size_t)bh * 64 * 64;

    for (int i = tid * 4; i < 4096; i += 1024) {
        float4 s = *(const float4*)(Sp + i);
        #pragma unroll
        for (int c = 1; c < NCH_; c++) {
            float4 p = *(const float4*)(Sp + (size_t)c * 4096 + i);
            s.x += p.x; s.y += p.y; s.z += p.z; s.w += p.w;
        }
        int row = i >> 6, col = i & 63;
        s.x *= 0.125f; s.y *= 0.125f; s.z *= 0.125f; s.w *= 0.125f;
        *(float4*)(sS + row * SQ_S + col) = s;
    }
    __syncthreads();

    if (tid < 64) {
        int r = tid;
        float m = -1e30f;
        for (int c = 0; c < 64; c++) m = fmaxf(m, sS[r * SQ_S + c]);
        float s = 0.f;
        float e[64];
        #pragma unroll 8
        for (int c = 0; c < 64; c++) {
            e[c] = __expf(sS[r * SQ_S + c] - m);
            s += e[c];
        }
        float inv = 1.f / s;
        #pragma unroll 8
        for (int c = 0; c < 64; c++)
            P[r * 64 + c] = to_tf32(e[c] * inv);
    }
}

// 3c: hv = P v over one N-chunk. grid (NCH_, B*NH), 256 thr
__global__ __launch_bounds__(256) void attn_pv_kernel()
{
    __shared__ float r0[64 * SV_S];   // v tile
    __shared__ float r1[64 * SQ_S];   // P

    int chunk = blockIdx.x;
    int bh = blockIdx.y;
    int b = bh / NH_, h = bh % NH_;
    const float* v = g_qkv + ((size_t)b * 3 * C_ + 2 * C_ + (size_t)h * HD_) * N_ + chunk * NCW_;
    float* hv = g_hv + ((size_t)b * C_ + (size_t)h * HD_) * N_ + chunk * NCW_;
    const float* P = g_P + (size_t)bh * 64 * 64;

    int tid  = threadIdx.x;
    int lane = tid & 31;
    int wid  = tid >> 5;
    int gid  = lane >> 2;
    int tig  = lane & 3;
    int m_warp = (wid & 3) * 16;
    int n_warp = (wid >> 2) * 32;

    // load P into smem
    for (int i = tid * 4; i < 4096; i += 1024) {
        int row = i >> 6, col = i & 63;
        *(float4*)(r1 + row * SQ_S + col) = *(const float4*)(P + i);
    }

    float4 rv[4];
    #pragma unroll
    for (int l = 0; l < 4; l++) {
        int idx = tid + l * 256;
        int row = idx >> 4, c4 = idx & 15;
        rv[l] = *(const float4*)(v + (size_t)row * N_ + c4 * 4);
    }
    __syncthreads();

    for (int n0 = 0; n0 < NCW_; n0 += 64) {
        #pragma unroll
        for (int l = 0; l < 4; l++) {
            int idx = tid + l * 256;
            int row = idx >> 4, c4 = idx & 15;
            *(float4*)(r0 + row * SV_S + c4 * 4) = rv[l];
        }
        __syncthreads();
        if (n0 + 64 < NCW_) {
            #pragma unroll
            for (int l = 0; l < 4; l++) {
                int idx = tid + l * 256;
                int row = idx >> 4, c4 = idx & 15;
                rv[l] = *(const float4*)(v + (size_t)row * N_ + n0 + 64 + c4 * 4);
            }
        }
        float a2[4][4];
        #pragma unroll
        for (int nt = 0; nt < 4; nt++)
            #pragma unroll
            for (int r = 0; r < 4; r++) a2[nt][r] = 0.f;

        #pragma unroll
        for (int ks = 0; ks < 8; ks++) {
            int kb = ks * 8;
            float a0 = r1[(m_warp + gid) * SQ_S + kb + tig];
            float a1 = r1[(m_warp + gid + 8) * SQ_S + kb + tig];
            float a2f = r1[(m_warp + gid) * SQ_S + kb + tig + 4];
            float a3 = r1[(m_warp + gid + 8) * SQ_S + kb + tig + 4];
            float bf[4][2];
            #pragma unroll
            for (int nt = 0; nt < 4; nt++) {
                int nn = n_warp + nt * 8 + gid;
                bf[nt][0] = r0[(kb + tig) * SV_S + nn];
                bf[nt][1] = r0[(kb + tig + 4) * SV_S + nn];
            }
            #pragma unroll
            for (int nt = 0; nt < 4; nt++)
                mma8(a2[nt], a0, a1, a2f, a3, bf[nt][0], bf[nt][1]);
        }
        #pragma unroll
        for (int nt = 0; nt < 4; nt++) {
            int col = n0 + n_warp + nt * 8 + tig * 2;
            int rA = m_warp + gid;
            *(float2*)(hv + (size_t)rA * N_ + col) =
                make_float2(to_tf32(a2[nt][0]), to_tf32(a2[nt][1]));
            *(float2*)(hv + (size_t)(rA + 8) * N_ + col) =
                make_float2(to_tf32(a2[nt][2]), to_tf32(a2[nt][3]));
        }
        __syncthreads();
    }
}

// ---------------------------------------------------------------------------
extern "C" void kernel_launch(void* const* d_in, const int* in_sizes, int n_in,
                              void* d_out, int out_size)
{
    const float* x     = (const float*)d_in[0];
    const float* gamma = (const float*)d_in[1];
    const float* beta  = (const float*)d_in[2];
    const float* w_qkv = (const float*)d_in[3];
    const float* b_qkv = (const float*)d_in[4];
    const float* w_out = (const float*)d_in[5];
    const float* b_out = (const float*)d_in[6];
    float* out = (float*)d_out;

    float* wq32;  cudaGetSymbolAddress((void**)&wq32, g_wq32);
    float* wo32;  cudaGetSymbolAddress((void**)&wo32, g_wo32);
    float* h32;   cudaGetSymbolAddress((void**)&h32,  g_h32);
    float* hv;    cudaGetSymbolAddress((void**)&hv,   g_hv);

    cvt_w_kernel<<<(3 * C_ * C_) / 256, 256>>>(w_qkv, w_out);
    gn_kernel<<<B_ * NG_, 256>>>(x, gamma, beta);
    gemm_tc<0><<<dim3(N_ / 128, (3 * C_) / 128, B_), 256>>>(wq32, h32, b_qkv, nullptr, nullptr);
    attn_qk_kernel<<<dim3(NCH_, B_ * NH_), 256>>>();
    attn_softmax_kernel<<<B_ * NH_, 256>>>();
    attn_pv_kernel<<<dim3(NCH_, B_ * NH_), 256>>>();
    gemm_tc<1><<<dim3(N_ / 128, C_ / 128, B_), 256>>>(wo32, hv, b_out, x, out);
}

// round 6
// speedup vs baseline: 3.7939x; 1.0003x over previous
#include <cuda_runtime.h>
#include <math.h>
#include <stdint.h>

#define B_   16
#define C_   512
#define N_   4096
#define NH_  8
#define HD_  64
#define NG_  8
#define CPG_ 64
#define EPS_ 1e-5f
#define KT_  (C_ / 8)        // 64 k-tiles of 8
#define NCH_ 8               // attention N-chunks
#define NCW_ (N_ / NCH_)     // 512 per chunk

// Scratch (allocation-free rule: static device globals)
__device__ float g_qkv[(size_t)B_ * 3 * C_ * N_];    // 384 MB, tf32-rounded
__device__ float g_hv [(size_t)B_ * C_ * N_];        // 128 MB, tf32-rounded
__device__ float g_h32[(size_t)B_ * C_ * N_];        // 128 MB, tf32(groupnorm(x))
__device__ float g_wq32[3 * C_ * C_];                // w_qkv, tf32, fragment-packed
__device__ float g_wo32[C_ * C_];                    // w_out, tf32, fragment-packed
__device__ float g_Sp[(size_t)B_ * NH_ * NCH_ * 64 * 64];  // partial S, 16.8 MB
__device__ float g_P [(size_t)B_ * NH_ * 64 * 64];         // softmax(P), tf32

// ---------------------------------------------------------------------------
// helpers
// ---------------------------------------------------------------------------
__device__ __forceinline__ float to_tf32(float x) {
    uint32_t u;
    asm("cvt.rna.tf32.f32 %0, %1;" : "=r"(u) : "f"(x));
    return __uint_as_float(u);
}

__device__ __forceinline__ void mma8(float c[4],
                                     float a0, float a1, float a2, float a3,
                                     float b0, float b1)
{
    asm volatile(
        "mma.sync.aligned.m16n8k8.row.col.f32.tf32.tf32.f32 "
        "{%0,%1,%2,%3}, {%4,%5,%6,%7}, {%8,%9}, {%0,%1,%2,%3};\n"
        : "+f"(c[0]), "+f"(c[1]), "+f"(c[2]), "+f"(c[3])
        : "r"(__float_as_uint(a0)), "r"(__float_as_uint(a1)),
          "r"(__float_as_uint(a2)), "r"(__float_as_uint(a3)),
          "r"(__float_as_uint(b0)), "r"(__float_as_uint(b1)));
}

__device__ __forceinline__ void cp16(uint32_t dst, const void* src) {
    asm volatile("cp.async.cg.shared.global [%0], [%1], 16;\n"
                 :: "r"(dst), "l"(src));
}
__device__ __forceinline__ void cp_commit() {
    asm volatile("cp.async.commit_group;\n" ::: "memory");
}
__device__ __forceinline__ void cp_wait0() {
    asm volatile("cp.async.wait_group 0;\n" ::: "memory");
}

// ---------------------------------------------------------------------------
// Kernel 0: convert + fragment-pack weights.
// Packed layout: Wp[mt_g][kt_g][lane][a_sel], mt_g=row/16, kt_g=col/8,
// lane = (row%8)*4 + (col%4), a_sel = (row%16>=8) | ((col%8>=4)<<1)
// ---------------------------------------------------------------------------
__device__ __forceinline__ void pack_one(float* dst, const float* src, int i, int M) {
    int row = i / C_, col = i % C_;
    int mt_g = row >> 4, kt_g = col >> 3;
    int row_in = row & 15, k_in = col & 7;
    int lane = (row_in & 7) * 4 + (k_in & 3);
    int a_sel = ((row_in >> 3) & 1) | (((k_in >> 2) & 1) << 1);
    dst[(((size_t)mt_g * KT_ + kt_g) * 32 + lane) * 4 + a_sel] = to_tf32(src[i]);
}

__global__ __launch_bounds__(256) void cvt_w_kernel(
    const float* __restrict__ wq, const float* __restrict__ wo)
{
    int i = blockIdx.x * 256 + threadIdx.x;
    if (i < 3 * C_ * C_) pack_one(g_wq32, wq, i, 3 * C_);
    if (i < C_ * C_)     pack_one(g_wo32, wo, i, C_);
}

// ---------------------------------------------------------------------------
// Kernel 1: group-norm stats + write h32 = tf32(x * scale + shift)
// ---------------------------------------------------------------------------
__global__ __launch_bounds__(256) void gn_kernel(
    const float* __restrict__ x,
    const float* __restrict__ gamma,
    const float* __restrict__ beta)
{
    int bg = blockIdx.x;
    int b = bg / NG_, g = bg % NG_;
    const float4* xp = (const float4*)(x + ((size_t)b * C_ + (size_t)g * CPG_) * N_);
    const int total4 = CPG_ * N_ / 4;

    float s = 0.f, ss = 0.f;
    for (int i = threadIdx.x; i < total4; i += 256) {
        float4 v = xp[i];
        s  += v.x + v.y + v.z + v.w;
        ss += v.x*v.x + v.y*v.y + v.z*v.z + v.w*v.w;
    }
    __shared__ float sh_s[256], sh_q[256];
    __shared__ float s_sc[CPG_], s_sf[CPG_];
    sh_s[threadIdx.x] = s; sh_q[threadIdx.x] = ss;
    __syncthreads();
    for (int off = 128; off > 0; off >>= 1) {
        if (threadIdx.x < off) {
            sh_s[threadIdx.x] += sh_s[threadIdx.x + off];
            sh_q[threadIdx.x] += sh_q[threadIdx.x + off];
        }
        __syncthreads();
    }
    float inv_n = 1.f / (float)(CPG_ * N_);
    float mean = sh_s[0] * inv_n;
    float var  = sh_q[0] * inv_n - mean * mean;
    float rstd = rsqrtf(var + EPS_);
    if (threadIdx.x < CPG_) {
        int c = g * CPG_ + threadIdx.x;
        float ga = gamma[c];
        s_sc[threadIdx.x] = rstd * ga;
        s_sf[threadIdx.x] = beta[c] - mean * rstd * ga;
    }
    __syncthreads();

    float4* hp = (float4*)(g_h32 + ((size_t)b * C_ + (size_t)g * CPG_) * N_);
    const int q4 = N_ / 4;
    for (int i = threadIdx.x; i < total4; i += 256) {
        int ch = i / q4;
        float sc = s_sc[ch], sf = s_sf[ch];
        float4 v = xp[i];
        hp[i] = make_float4(to_tf32(v.x*sc+sf), to_tf32(v.y*sc+sf),
                            to_tf32(v.z*sc+sf), to_tf32(v.w*sc+sf));
    }
}

// ---------------------------------------------------------------------------
// tf32 GEMM: 128x128 tile, BK=32, 8 warps of 64x32, cp.async double buffer,
// fragment-packed A (LDS.128 per m-tile), 2 CTAs/SM.
// ---------------------------------------------------------------------------
template<int MODE>
__global__ __launch_bounds__(256, 2) void gemm_tc(
    const float* __restrict__ Wp,      // packed tf32 [M/16][KT_][32][4]
    const float* __restrict__ Bmat,    // tf32 [B][C][N]
    const float* __restrict__ bias,
    const float* __restrict__ resid,
    float* __restrict__ Out)
{
    int b  = blockIdx.z;
    int bm = blockIdx.y;
    int bn = blockIdx.x;

    __shared__ __align__(16) float AsP[2 * 4096];      // packed A, 32 KB
    __shared__ __align__(16) float Bs[2][32][136];     // [k][n]

    const float* Bb = Bmat + (size_t)b * C_ * N_;

    int tid  = threadIdx.x;
    int lane = tid & 31;
    int wid  = tid >> 5;
    int gid  = lane >> 2;
    int tig  = lane & 3;
    int m_warp = (wid >> 2) * 64;
    int n_warp = (wid & 3) * 32;
    int mt_base = (wid >> 2) * 4;     // packed m-tile base for this warp

    uint32_t AsP_base = (uint32_t)__cvta_generic_to_shared(&AsP[0]);
    uint32_t Bs_base  = (uint32_t)__cvta_generic_to_shared(&Bs[0][0][0]);

    int bk = tid >> 5, bn4 = tid & 31;

    float acc[4][4][4];
    #pragma unroll
    for (int mt = 0; mt < 4; mt++)
        #pragma unroll
        for (int nt = 0; nt < 4; nt++)
            #pragma unroll
            for (int r = 0; r < 4; r++) acc[mt][nt][r] = 0.f;

    auto issue = [&](int k0, int s) {
        int kt0 = k0 >> 3;
        #pragma unroll
        for (int l = 0; l < 4; l++) {
            int f4 = tid + l * 256;          // 0..1023
            int mt = f4 >> 7;                // 0..7
            int rem = f4 & 127;              // float4 within 512-float region
            cp16(AsP_base + (((s * 4096) + mt * 512 + rem * 4)) * 4,
                 Wp + ((size_t)(bm * 8 + mt) * KT_ + kt0) * 128 + rem * 4);
        }
        #pragma unroll
        for (int l = 0; l < 4; l++) {
            int k = bk + l * 8;
            cp16(Bs_base + (((s * 32 + k) * 136) + bn4 * 4) * 4,
                 Bb + (size_t)(k0 + k) * N_ + bn * 128 + bn4 * 4);
        }
        cp_commit();
    };

    issue(0, 0);
    int buf = 0;
    for (int k0 = 0; k0 < C_; k0 += 32) {
        cp_wait0();
        __syncthreads();
        if (k0 + 32 < C_) issue(k0 + 32, buf ^ 1);

        #pragma unroll
        for (int ks = 0; ks < 4; ks++) {
            int kb = ks * 8;
            float4 af[4];
            float bf[4][2];
            #pragma unroll
            for (int mt = 0; mt < 4; mt++)
                af[mt] = *(const float4*)(AsP + buf * 4096 +
                                          ((mt_base + mt) * 4 + ks) * 128 + lane * 4);
            #pragma unroll
            for (int nt = 0; nt < 4; nt++) {
                int n0 = n_warp + nt * 8 + gid;
                bf[nt][0] = Bs[buf][kb + tig][n0];
                bf[nt][1] = Bs[buf][kb + tig + 4][n0];
            }
            #pragma unroll
            for (int mt = 0; mt < 4; mt++)
                #pragma unroll
                for (int nt = 0; nt < 4; nt++)
                    mma8(acc[mt][nt], af[mt].x, af[mt].y, af[mt].z, af[mt].w,
                         bf[nt][0], bf[nt][1]);
        }
        buf ^= 1;
    }

    // epilogue
    #pragma unroll
    for (int mt = 0; mt < 4; mt++) {
        int r0  = m_warp + mt * 16 + gid;
        int gr0 = bm * 128 + r0;
        float bi0 = bias[gr0];
        float bi1 = bias[gr0 + 8];
        #pragma unroll
        for (int nt = 0; nt < 4; nt++) {
            int col = n_warp + nt * 8 + tig * 2;
            if (MODE == 0) {
                float* o = g_qkv + ((size_t)b * 3 * C_ + gr0) * N_ + bn * 128 + col;
                *(float2*)o =
                    make_float2(to_tf32(acc[mt][nt][0] + bi0), to_tf32(acc[mt][nt][1] + bi0));
                *(float2*)(o + 8 * N_) =
                    make_float2(to_tf32(acc[mt][nt][2] + bi1), to_tf32(acc[mt][nt][3] + bi1));
            } else {
                size_t base = ((size_t)b * C_ + gr0) * N_ + bn * 128 + col;
                float2 x0 = *(const float2*)(resid + base);
                float2 x1 = *(const float2*)(resid + base + 8 * N_);
                *(float2*)(Out + base) =
                    make_float2(acc[mt][nt][0] + bi0 + x0.x, acc[mt][nt][1] + bi0 + x0.y);
                *(float2*)(Out + base + 8 * N_) =
                    make_float2(acc[mt][nt][2] + bi1 + x1.x, acc[mt][nt][3] + bi1 + x1.y);
            }
        }
    }
}

// ---------------------------------------------------------------------------
// Attention, split for occupancy. Common warp layout: 8 warps, S-tile 64x64:
// m_warp=(wid&3)*16 rows, n_warp=(wid>>2)*32 cols.
// ---------------------------------------------------------------------------
#define SQ_S 68
#define SV_S 72

// 3a: partial S over one N-chunk. grid (NCH_, B*NH), 256 thr
__global__ __launch_bounds__(256) void attn_qk_kernel()
{
    __shared__ float r0[64 * SQ_S];   // q tiles
    __shared__ float r1[64 * SQ_S];   // k tiles

    int chunk = blockIdx.x;
    int bh = blockIdx.y;
    int b = bh / NH_, h = bh % NH_;
    const float* q = g_qkv + ((size_t)b * 3 * C_ + 0 * C_ + (size_t)h * HD_) * N_ + chunk * NCW_;
    const float* k = g_qkv + ((size_t)b * 3 * C_ + 1 * C_ + (size_t)h * HD_) * N_ + chunk * NCW_;

    int tid  = threadIdx.x;
    int lane = tid & 31;
    int wid  = tid >> 5;
    int gid  = lane >> 2;
    int tig  = lane & 3;
    int m_warp = (wid & 3) * 16;
    int n_warp = (wid >> 2) * 32;

    float acc[4][4];
    #pragma unroll
    for (int nt = 0; nt < 4; nt++)
        #pragma unroll
        for (int r = 0; r < 4; r++) acc[nt][r] = 0.f;

    float4 rq[4], rk[4];
    #pragma unroll
    for (int l = 0; l < 4; l++) {
        int idx = tid + l * 256;
        int row = idx >> 4, c4 = idx & 15;
        rq[l] = *(const float4*)(q + (size_t)row * N_ + c4 * 4);
        rk[l] = *(const float4*)(k + (size_t)row * N_ + c4 * 4);
    }

    for (int n0 = 0; n0 < NCW_; n0 += 64) {
        #pragma unroll
        for (int l = 0; l < 4; l++) {
            int idx = tid + l * 256;
            int row = idx >> 4, c4 = idx & 15;
            *(float4*)(r0 + row * SQ_S + c4 * 4) = rq[l];
            *(float4*)(r1 + row * SQ_S + c4 * 4) = rk[l];
        }
        __syncthreads();
        if (n0 + 64 < NCW_) {
            #pragma unroll
            for (int l = 0; l < 4; l++) {
                int idx = tid + l * 256;
                int row = idx >> 4, c4 = idx & 15;
                rq[l] = *(const float4*)(q + (size_t)row * N_ + n0 + 64 + c4 * 4);
                rk[l] = *(const float4*)(k + (size_t)row * N_ + n0 + 64 + c4 * 4);
            }
        }
        #pragma unroll
        for (int ks = 0; ks < 8; ks++) {
            int kb = ks * 8;
            float a0 = r0[(m_warp + gid) * SQ_S + kb + tig];
            float a1 = r0[(m_warp + gid + 8) * SQ_S + kb + tig];
            float a2 = r0[(m_warp + gid) * SQ_S + kb + tig + 4];
            float a3 = r0[(m_warp + gid + 8) * SQ_S + kb + tig + 4];
            float bf[4][2];
            #pragma unroll
            for (int nt = 0; nt < 4; nt++) {
                int e0 = n_warp + nt * 8 + gid;
                bf[nt][0] = r1[e0 * SQ_S + kb + tig];
                bf[nt][1] = r1[e0 * SQ_S + kb + tig + 4];
            }
            #pragma unroll
            for (int nt = 0; nt < 4; nt++)
                mma8(acc[nt], a0, a1, a2, a3, bf[nt][0], bf[nt][1]);
        }
        __syncthreads();
    }

    float* Sp = g_Sp + ((size_t)bh * NCH_ + chunk) * 64 * 64;
    #pragma unroll
    for (int nt = 0; nt < 4; nt++) {
        int col = n_warp + nt * 8 + tig * 2;
        int rA = m_warp + gid;
        *(float2*)(Sp + rA * 64 + col)       = make_float2(acc[nt][0], acc[nt][1]);
        *(float2*)(Sp + (rA + 8) * 64 + col) = make_float2(acc[nt][2], acc[nt][3]);
    }
}

// 3b: reduce partials + softmax -> P (tf32). grid B*NH, 256 thr
__global__ __launch_bounds__(256) void attn_softmax_kernel()
{
    __shared__ float sS[64 * SQ_S];
    int bh = blockIdx.x;
    int tid = threadIdx.x;
    const float* Sp = g_Sp + (size_t)bh * NCH_ * 64 * 64;
    float* P = g_P + (size_t)bh * 64 * 64;

    for (int i = tid * 4; i < 4096; i += 1024) {
        float4 s = *(const float4*)(Sp + i);
        #pragma unroll
        for (int c = 1; c < NCH_; c++) {
            float4 p = *(const float4*)(Sp + (size_t)c * 4096 + i);
            s.x += p.x; s.y += p.y; s.z += p.z; s.w += p.w;
        }
        int row = i >> 6, col = i & 63;
        s.x *= 0.125f; s.y *= 0.125f; s.z *= 0.125f; s.w *= 0.125f;
        *(float4*)(sS + row * SQ_S + col) = s;
    }
    __syncthreads();

    if (tid < 64) {
        int r = tid;
        float m = -1e30f;
        for (int c = 0; c < 64; c++) m = fmaxf(m, sS[r * SQ_S + c]);
        float s = 0.f;
        float e[64];
        #pragma unroll 8
        for (int c = 0; c < 64; c++) {
            e[c] = __expf(sS[r * SQ_S + c] - m);
            s += e[c];
        }
        float inv = 1.f / s;
        #pragma unroll 8
        for (int c = 0; c < 64; c++)
            P[r * 64 + c] = to_tf32(e[c] * inv);
    }
}

// 3c: hv = P v over one N-chunk. grid (NCH_, B*NH), 256 thr
__global__ __launch_bounds__(256) void attn_pv_kernel()
{
    __shared__ float r0[64 * SV_S];   // v tile
    __shared__ float r1[64 * SQ_S];   // P

    int chunk = blockIdx.x;
    int bh = blockIdx.y;
    int b = bh / NH_, h = bh % NH_;
    const float* v = g_qkv + ((size_t)b * 3 * C_ + 2 * C_ + (size_t)h * HD_) * N_ + chunk * NCW_;
    float* hv = g_hv + ((size_t)b * C_ + (size_t)h * HD_) * N_ + chunk * NCW_;
    const float* P = g_P + (size_t)bh * 64 * 64;

    int tid  = threadIdx.x;
    int lane = tid & 31;
    int wid  = tid >> 5;
    int gid  = lane >> 2;
    int tig  = lane & 3;
    int m_warp = (wid & 3) * 16;
    int n_warp = (wid >> 2) * 32;

    // load P into smem
    for (int i = tid * 4; i < 4096; i += 1024) {
        int row = i >> 6, col = i & 63;
        *(float4*)(r1 + row * SQ_S + col) = *(const float4*)(P + i);
    }

    float4 rv[4];
    #pragma unroll
    for (int l = 0; l < 4; l++) {
        int idx = tid + l * 256;
        int row = idx >> 4, c4 = idx & 15;
        rv[l] = *(const float4*)(v + (size_t)row * N_ + c4 * 4);
    }
    __syncthreads();

    for (int n0 = 0; n0 < NCW_; n0 += 64) {
        #pragma unroll
        for (int l = 0; l < 4; l++) {
            int idx = tid + l * 256;
            int row = idx >> 4, c4 = idx & 15;
            *(float4*)(r0 + row * SV_S + c4 * 4) = rv[l];
        }
        __syncthreads();
        if (n0 + 64 < NCW_) {
            #pragma unroll
            for (int l = 0; l < 4; l++) {
                int idx = tid + l * 256;
                int row = idx >> 4, c4 = idx & 15;
                rv[l] = *(const float4*)(v + (size_t)row * N_ + n0 + 64 + c4 * 4);
            }
        }
        float a2[4][4];
        #pragma unroll
        for (int nt = 0; nt < 4; nt++)
            #pragma unroll
            for (int r = 0; r < 4; r++) a2[nt][r] = 0.f;

        #pragma unroll
        for (int ks = 0; ks < 8; ks++) {
            int kb = ks * 8;
            float a0 = r1[(m_warp + gid) * SQ_S + kb + tig];
            float a1 = r1[(m_warp + gid + 8) * SQ_S + kb + tig];
            float a2f = r1[(m_warp + gid) * SQ_S + kb + tig + 4];
            float a3 = r1[(m_warp + gid + 8) * SQ_S + kb + tig + 4];
            float bf[4][2];
            #pragma unroll
            for (int nt = 0; nt < 4; nt++) {
                int nn = n_warp + nt * 8 + gid;
                bf[nt][0] = r0[(kb + tig) * SV_S + nn];
                bf[nt][1] = r0[(kb + tig + 4) * SV_S + nn];
            }
            #pragma unroll
            for (int nt = 0; nt < 4; nt++)
                mma8(a2[nt], a0, a1, a2f, a3, bf[nt][0], bf[nt][1]);
        }
        #pragma unroll
        for (int nt = 0; nt < 4; nt++) {
            int col = n0 + n_warp + nt * 8 + tig * 2;
            int rA = m_warp + gid;
            *(float2*)(hv + (size_t)rA * N_ + col) =
                make_float2(to_tf32(a2[nt][0]), to_tf32(a2[nt][1]));
            *(float2*)(hv + (size_t)(rA + 8) * N_ + col) =
                make_float2(to_tf32(a2[nt][2]), to_tf32(a2[nt][3]));
        }
        __syncthreads();
    }
}

// ---------------------------------------------------------------------------
extern "C" void kernel_launch(void* const* d_in, const int* in_sizes, int n_in,
                              void* d_out, int out_size)
{
    const float* x     = (const float*)d_in[0];
    const float* gamma = (const float*)d_in[1];
    const float* beta  = (const float*)d_in[2];
    const float* w_qkv = (const float*)d_in[3];
    const float* b_qkv = (const float*)d_in[4];
    const float* w_out = (const float*)d_in[5];
    const float* b_out = (const float*)d_in[6];
    float* out = (float*)d_out;

    float* wq32;  cudaGetSymbolAddress((void**)&wq32, g_wq32);
    float* wo32;  cudaGetSymbolAddress((void**)&wo32, g_wo32);
    float* h32;   cudaGetSymbolAddress((void**)&h32,  g_h32);
    float* hv;    cudaGetSymbolAddress((void**)&hv,   g_hv);

    cvt_w_kernel<<<(3 * C_ * C_) / 256, 256>>>(w_qkv, w_out);
    gn_kernel<<<B_ * NG_, 256>>>(x, gamma, beta);
    gemm_tc<0><<<dim3(N_ / 128, (3 * C_) / 128, B_), 256>>>(wq32, h32, b_qkv, nullptr, nullptr);
    attn_qk_kernel<<<dim3(NCH_, B_ * NH_), 256>>>();
    attn_softmax_kernel<<<B_ * NH_, 256>>>();
    attn_pv_kernel<<<dim3(NCH_, B_ * NH_), 256>>>();
    gemm_tc<1><<<dim3(N_ / 128, C_ / 128, B_), 256>>>(wo32, hv, b_out, x, out);
}

// round 9
// speedup vs baseline: 4.2994x; 1.1332x over previous
#include <cuda_runtime.h>
#include <cuda_bf16.h>
#include <math.h>
#include <stdint.h>

#define B_   16
#define C_   512
#define N_   4096
#define NH_  8
#define HD_  64
#define NG_  8
#define CPG_ 64
#define EPS_ 1e-5f
#define KT_  (C_ / 8)        // 64 k-tiles of 8 (tf32 packing)
#define NCH_ 8
#define NCW_ (N_ / NCH_)

// Scratch (allocation-free: static device globals)
__device__ float    g_qkv[(size_t)B_ * 3 * C_ * N_];      // [b][3C][N] tf32-rounded
__device__ uint32_t g_hv2[(size_t)B_ * (C_ / 2) * N_];    // [b][c2][N] bf16x2 (k-pair interleave)
__device__ float    g_sc[B_ * C_], g_sf[B_ * C_];
__device__ float    g_wqb[(size_t)B_ * 3 * C_ * C_];      // per-batch scaled w_qkv, tf32, frag-packed
__device__ float    g_bqb[B_ * 3 * C_];                   // per-batch qkv bias (b + W@sf)
__device__ uint32_t g_wo2[C_ * C_ / 2];                   // w_out bf16, frag-packed (m16n8k16)
__device__ float    g_Sp[(size_t)B_ * NH_ * NCH_ * 64 * 64];
__device__ float    g_P [(size_t)B_ * NH_ * 64 * 64];

// ---------------- helpers ----------------
__device__ __forceinline__ float to_tf32(float x) {
    uint32_t u; asm("cvt.rna.tf32.f32 %0, %1;" : "=r"(u) : "f"(x));
    return __uint_as_float(u);
}
__device__ __forceinline__ void mma8(float c[4], float a0, float a1, float a2, float a3,
                                     float b0, float b1) {
    asm volatile(
        "mma.sync.aligned.m16n8k8.row.col.f32.tf32.tf32.f32 "
        "{%0,%1,%2,%3}, {%4,%5,%6,%7}, {%8,%9}, {%0,%1,%2,%3};\n"
        : "+f"(c[0]), "+f"(c[1]), "+f"(c[2]), "+f"(c[3])
        : "r"(__float_as_uint(a0)), "r"(__float_as_uint(a1)),
          "r"(__float_as_uint(a2)), "r"(__float_as_uint(a3)),
          "r"(__float_as_uint(b0)), "r"(__float_as_uint(b1)));
}
__device__ __forceinline__ void mma16bf(float c[4], uint32_t a0, uint32_t a1,
                                        uint32_t a2, uint32_t a3,
                                        uint32_t b0, uint32_t b1) {
    asm volatile(
        "mma.sync.aligned.m16n8k16.row.col.f32.bf16.bf16.f32 "
        "{%0,%1,%2,%3}, {%4,%5,%6,%7}, {%8,%9}, {%0,%1,%2,%3};\n"
        : "+f"(c[0]), "+f"(c[1]), "+f"(c[2]), "+f"(c[3])
        : "r"(a0), "r"(a1), "r"(a2), "r"(a3), "r"(b0), "r"(b1));
}
__device__ __forceinline__ void cp16(uint32_t dst, const void* src) {
    asm volatile("cp.async.cg.shared.global [%0], [%1], 16;\n" :: "r"(dst), "l"(src));
}
__device__ __forceinline__ void cp_commit() {
    asm volatile("cp.async.commit_group;\n" ::: "memory");
}
__device__ __forceinline__ void cp_wait0() {
    asm volatile("cp.async.wait_group 0;\n" ::: "memory");
}
__device__ __forceinline__ uint32_t packbf2(float lo, float hi) {
    __nv_bfloat162 v = __floats2bfloat162_rn(lo, hi);   // .x = lo (lower 16 bits)
    return *(uint32_t*)&v;
}

// ---------------- kernel 1: groupnorm stats -> sc/sf ----------------
__global__ __launch_bounds__(256) void gn_stats_kernel(
    const float* __restrict__ x, const float* __restrict__ gamma,
    const float* __restrict__ beta)
{
    int bg = blockIdx.x, b = bg / NG_, g = bg % NG_;
    int tid = threadIdx.x;
    const float4* xp = (const float4*)(x + ((size_t)b * C_ + (size_t)g * CPG_) * N_);
    const int total4 = CPG_ * N_ / 4;

    float s = 0.f, ss = 0.f;
    for (int i = tid; i < total4; i += 256) {
        float4 v = xp[i];
        s += v.x + v.y + v.z + v.w;
        ss += v.x*v.x + v.y*v.y + v.z*v.z + v.w*v.w;
    }
    __shared__ float sh_s[256], sh_q[256];
    sh_s[tid] = s; sh_q[tid] = ss;
    __syncthreads();
    for (int off = 128; off > 0; off >>= 1) {
        if (tid < off) { sh_s[tid] += sh_s[tid+off]; sh_q[tid] += sh_q[tid+off]; }
        __syncthreads();
    }
    float inv_n = 1.f / (float)(CPG_ * N_);
    float mean = sh_s[0] * inv_n;
    float rstd = rsqrtf(sh_q[0] * inv_n - mean * mean + EPS_);
    if (tid < CPG_) {
        int c = g * CPG_ + tid;
        float ga = gamma[c];
        g_sc[b * C_ + c] = rstd * ga;
        g_sf[b * C_ + c] = beta[c] - mean * rstd * ga;
    }
}

// ---------------- kernel 2: per-batch scaled + frag-packed qkv weights ----------------
__global__ __launch_bounds__(256) void wscale_kernel(
    const float* __restrict__ W, const float* __restrict__ bq)
{
    __shared__ float sp[8192];
    int mt_g = blockIdx.x;            // 0..95
    int b    = blockIdx.y;
    int tid  = threadIdx.x;
    const float* scl = g_sc + b * C_;
    const float* sfl = g_sf + b * C_;

    for (int i = tid; i < 8192; i += 256) {
        int o_in = i >> 9, c = i & 511;
        float w = W[(size_t)(mt_g * 16 + o_in) * C_ + c];
        int kt_g = c >> 3, k_in = c & 7;
        int lane_p = (o_in & 7) * 4 + (k_in & 3);
        int a_sel = ((o_in >> 3) & 1) | (((k_in >> 2) & 1) << 1);
        sp[(kt_g * 32 + lane_p) * 4 + a_sel] = to_tf32(w * scl[c]);
    }
    __syncthreads();

    int wid = tid >> 5, lane = tid & 31;
    for (int oo = 0; oo < 2; oo++) {
        int o_in = wid * 2 + oo;
        int o = mt_g * 16 + o_in;
        float acc = 0.f;
        for (int j = 0; j < 16; j++) {
            int c = j * 32 + lane;
            acc += W[(size_t)o * C_ + c] * sfl[c];
        }
        #pragma unroll
        for (int off = 16; off > 0; off >>= 1)
            acc += __shfl_xor_sync(0xFFFFFFFF, acc, off);
        if (lane == 0) g_bqb[b * 3 * C_ + o] = bq[o] + acc;
    }

    float* dst = g_wqb + (size_t)b * 3 * C_ * C_ + (size_t)mt_g * 8192;
    for (int i = tid; i < 2048; i += 256)
        *(float4*)(dst + i * 4) = *(float4*)(sp + i * 4);
}

// ---------------- kernel 3: w_out -> bf16 frag-packed ----------------
__global__ __launch_bounds__(256) void cvt_wo_kernel(const float* __restrict__ wo)
{
    int w = blockIdx.x * 256 + threadIdx.x;       // word id
    if (w >= C_ * C_ / 2) return;
    int sel = w & 3, lane_p = (w >> 2) & 31, kt_g = (w >> 7) & 31, mt_g = w >> 12;
    int gid = lane_p >> 2, tig = lane_p & 3;
    int row = mt_g * 16 + gid + ((sel & 1) << 3);
    int k = kt_g * 16 + tig * 2 + ((sel >> 1) << 3);
    g_wo2[w] = packbf2(wo[(size_t)row * C_ + k], wo[(size_t)row * C_ + k + 1]);
}

// ---------------- tf32 GEMM (qkv): 128x128, BK=32, frag-packed A, 2 CTA/SM ----------------
__global__ __launch_bounds__(256, 2) void gemm_qkv(
    const float* __restrict__ x)
{
    int b = blockIdx.z, bm = blockIdx.y, bn = blockIdx.x;
    __shared__ __align__(16) float AsP[2 * 4096];
    __shared__ __align__(16) float Bs[2][32][136];

    const float* Wp = g_wqb + (size_t)b * 3 * C_ * C_;
    const float* Bb = x + (size_t)b * C_ * N_;
    const float* bias = g_bqb + b * 3 * C_;

    int tid = threadIdx.x, lane = tid & 31, wid = tid >> 5;
    int gid = lane >> 2, tig = lane & 3;
    int m_warp = (wid >> 2) * 64, n_warp = (wid & 3) * 32;
    int mt_base = (wid >> 2) * 4;

    uint32_t AsP_base = (uint32_t)__cvta_generic_to_shared(&AsP[0]);
    uint32_t Bs_base  = (uint32_t)__cvta_generic_to_shared(&Bs[0][0][0]);
    int bk = tid >> 5, bn4 = tid & 31;

    float acc[4][4][4];
    #pragma unroll
    for (int mt = 0; mt < 4; mt++)
        #pragma unroll
        for (int nt = 0; nt < 4; nt++)
            #pragma unroll
            for (int r = 0; r < 4; r++) acc[mt][nt][r] = 0.f;

    auto issue = [&](int k0, int s) {
        int kt0 = k0 >> 3;
        #pragma unroll
        for (int l = 0; l < 4; l++) {
            int f4 = tid + l * 256;
            int mt = f4 >> 7, rem = f4 & 127;
            cp16(AsP_base + ((s * 4096) + mt * 512 + rem * 4) * 4,
                 Wp + ((size_t)(bm * 8 + mt) * KT_ + kt0) * 128 + rem * 4);
        }
        #pragma unroll
        for (int l = 0; l < 4; l++) {
            int k = bk + l * 8;
            cp16(Bs_base + (((s * 32 + k) * 136) + bn4 * 4) * 4,
                 Bb + (size_t)(k0 + k) * N_ + bn * 128 + bn4 * 4);
        }
        cp_commit();
    };

    issue(0, 0);
    int buf = 0;
    for (int k0 = 0; k0 < C_; k0 += 32) {
        cp_wait0();
        __syncthreads();
        if (k0 + 32 < C_) issue(k0 + 32, buf ^ 1);

        #pragma unroll
        for (int ks = 0; ks < 4; ks++) {
            int kb = ks * 8;
            float4 af[4];
            float bf[4][2];
            #pragma unroll
            for (int mt = 0; mt < 4; mt++)
                af[mt] = *(const float4*)(AsP + buf * 4096 +
                                          ((mt_base + mt) * 4 + ks) * 128 + lane * 4);
            #pragma unroll
            for (int nt = 0; nt < 4; nt++) {
                int n0 = n_warp + nt * 8 + gid;
                bf[nt][0] = Bs[buf][kb + tig][n0];
                bf[nt][1] = Bs[buf][kb + tig + 4][n0];
            }
            #pragma unroll
            for (int mt = 0; mt < 4; mt++)
                #pragma unroll
                for (int nt = 0; nt < 4; nt++)
                    mma8(acc[mt][nt], af[mt].x, af[mt].y, af[mt].z, af[mt].w,
                         bf[nt][0], bf[nt][1]);
        }
        buf ^= 1;
    }

    #pragma unroll
    for (int mt = 0; mt < 4; mt++) {
        int r0 = m_warp + mt * 16 + gid;
        int gr0 = bm * 128 + r0;
        float bi0 = bias[gr0], bi1 = bias[gr0 + 8];
        #pragma unroll
        for (int nt = 0; nt < 4; nt++) {
            int col = n_warp + nt * 8 + tig * 2;
            float* o = g_qkv + ((size_t)b * 3 * C_ + gr0) * N_ + bn * 128 + col;
            *(float2*)o =
                make_float2(to_tf32(acc[mt][nt][0] + bi0), to_tf32(acc[mt][nt][1] + bi0));
            *(float2*)(o + 8 * N_) =
                make_float2(to_tf32(acc[mt][nt][2] + bi1), to_tf32(acc[mt][nt][3] + bi1));
        }
    }
}

// ---------------- bf16 GEMM (out proj): 128x128, BK=32, 2 CTA/SM ----------------
__global__ __launch_bounds__(256, 2) void gemm_out(
    const float* __restrict__ bias, const float* __restrict__ resid,
    float* __restrict__ Out)
{
    int b = blockIdx.z, bm = blockIdx.y, bn = blockIdx.x;
    __shared__ __align__(16) uint32_t As2[2 * 2048];       // frag-packed A
    __shared__ __align__(16) uint32_t Bs2[2][16][132];     // bf16x2 [k2][n]

    int tid = threadIdx.x, lane = tid & 31, wid = tid >> 5;
    int gid = lane >> 2, tig = lane & 3;
    int m_warp = (wid >> 2) * 64, n_warp = (wid & 3) * 32;
    int mt_base = (wid >> 2) * 4;

    uint32_t As_base = (uint32_t)__cvta_generic_to_shared(&As2[0]);
    uint32_t Bs_base = (uint32_t)__cvta_generic_to_shared(&Bs2[0][0][0]);

    float acc[4][4][4];
    #pragma unroll
    for (int mt = 0; mt < 4; mt++)
        #pragma unroll
        for (int nt = 0; nt < 4; nt++)
            #pragma unroll
            for (int r = 0; r < 4; r++) acc[mt][nt][r] = 0.f;

    auto issue = [&](int kt, int s) {
        #pragma unroll
        for (int l = 0; l < 2; l++) {
            int c = tid + l * 256;
            int mt = c >> 6, w4 = c & 63;
            cp16(As_base + ((s * 2048) + mt * 256 + w4 * 4) * 4,
                 g_wo2 + ((size_t)(bm * 8 + mt) * 32 + kt * 2) * 128 + w4 * 4);
        }
        #pragma unroll
        for (int l = 0; l < 2; l++) {
            int c = tid + l * 256;
            int r = c >> 5, n4 = c & 31;
            cp16(Bs_base + ((s * 16 + r) * 132 + n4 * 4) * 4,
                 g_hv2 + ((size_t)b * 256 + kt * 16 + r) * N_ + bn * 128 + n4 * 4);
        }
        cp_commit();
    };

    issue(0, 0);
    int buf = 0;
    for (int kt = 0; kt < 16; kt++) {
        cp_wait0();
        __syncthreads();
        if (kt + 1 < 16) issue(kt + 1, buf ^ 1);

        #pragma unroll
        for (int ks = 0; ks < 2; ks++) {
            int kb2 = ks * 8;
            uint4 af[4];
            uint32_t bf[4][2];
            #pragma unroll
            for (int mt = 0; mt < 4; mt++)
                af[mt] = *(const uint4*)(As2 + buf * 2048 +
                                         (mt_base + mt) * 256 + ks * 128 + lane * 4);
            #pragma unroll
            for (int nt = 0; nt < 4; nt++) {
                int n0 = n_warp + nt * 8 + gid;
                bf[nt][0] = Bs2[buf][kb2 + tig][n0];
                bf[nt][1] = Bs2[buf][kb2 + tig + 4][n0];
            }
            #pragma unroll
            for (int mt = 0; mt < 4; mt++)
                #pragma unroll
                for (int nt = 0; nt < 4; nt++)
                    mma16bf(acc[mt][nt], af[mt].x, af[mt].y, af[mt].z, af[mt].w,
                            bf[nt][0], bf[nt][1]);
        }
        buf ^= 1;
    }

    #pragma unroll
    for (int mt = 0; mt < 4; mt++) {
        int r0 = m_warp + mt * 16 + gid;
        int gr0 = bm * 128 + r0;
        float bi0 = bias[gr0], bi1 = bias[gr0 + 8];
        #pragma unroll
        for (int nt = 0; nt < 4; nt++) {
            int col = n_warp + nt * 8 + tig * 2;
            size_t base = ((size_t)b * C_ + gr0) * N_ + bn * 128 + col;
            float2 x0 = *(const float2*)(resid + base);
            float2 x1 = *(const float2*)(resid + base + 8 * N_);
            *(float2*)(Out + base) =
                make_float2(acc[mt][nt][0] + bi0 + x0.x, acc[mt][nt][1] + bi0 + x0.y);
            *(float2*)(Out + base + 8 * N_) =
                make_float2(acc[mt][nt][2] + bi1 + x1.x, acc[mt][nt][3] + bi1 + x1.y);
        }
    }
}

// ---------------- attention (mma.sync tf32, split) ----------------
#define SQ_S 68
#define SV_S 72

__global__ __launch_bounds__(256) void attn_qk_kernel()
{
    __shared__ float r0[64 * SQ_S], r1[64 * SQ_S];
    int chunk = blockIdx.x, bh = blockIdx.y;
    int b = bh / NH_, h = bh % NH_;
    const float* q = g_qkv + ((size_t)b * 3 * C_ + (size_t)h * HD_) * N_ + chunk * NCW_;
    const float* k = g_qkv + ((size_t)b * 3 * C_ + C_ + (size_t)h * HD_) * N_ + chunk * NCW_;

    int tid = threadIdx.x, lane = tid & 31, wid = tid >> 5;
    int gid = lane >> 2, tig = lane & 3;
    int m_warp = (wid & 3) * 16, n_warp = (wid >> 2) * 32;

    float acc[4][4];
    #pragma unroll
    for (int nt = 0; nt < 4; nt++)
        #pragma unroll
        for (int r = 0; r < 4; r++) acc[nt][r] = 0.f;

    float4 rq[4], rk[4];
    #pragma unroll
    for (int l = 0; l < 4; l++) {
        int idx = tid + l * 256, row = idx >> 4, c4 = idx & 15;
        rq[l] = *(const float4*)(q + (size_t)row * N_ + c4 * 4);
        rk[l] = *(const float4*)(k + (size_t)row * N_ + c4 * 4);
    }
    for (int n0 = 0; n0 < NCW_; n0 += 64) {
        #pragma unroll
        for (int l = 0; l < 4; l++) {
            int idx = tid + l * 256, row = idx >> 4, c4 = idx & 15;
            *(float4*)(r0 + row * SQ_S + c4 * 4) = rq[l];
            *(float4*)(r1 + row * SQ_S + c4 * 4) = rk[l];
        }
        __syncthreads();
        if (n0 + 64 < NCW_) {
            #pragma unroll
            for (int l = 0; l < 4; l++) {
                int idx = tid + l * 256, row = idx >> 4, c4 = idx & 15;
                rq[l] = *(const float4*)(q + (size_t)row * N_ + n0 + 64 + c4 * 4);
                rk[l] = *(const float4*)(k + (size_t)row * N_ + n0 + 64 + c4 * 4);
            }
        }
        #pragma unroll
        for (int ks = 0; ks < 8; ks++) {
            int kb = ks * 8;
            float a0 = r0[(m_warp+gid)*SQ_S + kb + tig];
            float a1 = r0[(m_warp+gid+8)*SQ_S + kb + tig];
            float a2 = r0[(m_warp+gid)*SQ_S + kb + tig + 4];
            float a3 = r0[(m_warp+gid+8)*SQ_S + kb + tig + 4];
            float bf[4][2];
            #pragma unroll
            for (int nt = 0; nt < 4; nt++) {
                int e0 = n_warp + nt * 8 + gid;
                bf[nt][0] = r1[e0*SQ_S + kb + tig];
                bf[nt][1] = r1[e0*SQ_S + kb + tig + 4];
            }
            #pragma unroll
            for (int nt = 0; nt < 4; nt++)
                mma8(acc[nt], a0, a1, a2, a3, bf[nt][0], bf[nt][1]);
        }
        __syncthreads();
    }
    float* Sp = g_Sp + ((size_t)bh * NCH_ + chunk) * 4096;
    #pragma unroll
    for (int nt = 0; nt < 4; nt++) {
        int col = n_warp + nt * 8 + tig * 2, rA = m_warp + gid;
        *(float2*)(Sp + rA * 64 + col)       = make_float2(acc[nt][0], acc[nt][1]);
        *(float2*)(Sp + (rA + 8) * 64 + col) = make_float2(acc[nt][2], acc[nt][3]);
    }
}

__global__ __launch_bounds__(256) void attn_softmax_kernel()
{
    __shared__ float sS[64 * SQ_S];
    int bh = blockIdx.x, tid = threadIdx.x;
    const float* Sp = g_Sp + (size_t)bh * NCH_ * 4096;
    float* P = g_P + (size_t)bh * 4096;

    for (int i = tid * 4; i < 4096; i += 1024) {
        float4 s = *(const float4*)(Sp + i);
        #pragma unroll
        for (int c = 1; c < NCH_; c++) {
            float4 p = *(const float4*)(Sp + (size_t)c * 4096 + i);
            s.x += p.x; s.y += p.y; s.z += p.z; s.w += p.w;
        }
        int row = i >> 6, col = i & 63;
        s.x *= 0.125f; s.y *= 0.125f; s.z *= 0.125f; s.w *= 0.125f;
        *(float4*)(sS + row * SQ_S + col) = s;
    }
    __syncthreads();
    if (tid < 64) {
        int r = tid;
        float m = -1e30f;
        for (int c = 0; c < 64; c++) m = fmaxf(m, sS[r * SQ_S + c]);
        float s = 0.f, e[64];
        #pragma unroll 8
        for (int c = 0; c < 64; c++) { e[c] = __expf(sS[r * SQ_S + c] - m); s += e[c]; }
        float inv = 1.f / s;
        #pragma unroll 8
        for (int c = 0; c < 64; c++) P[r * 64 + c] = to_tf32(e[c] * inv);
    }
}

// pv: hv tile -> bf16x2 k-pair interleaved g_hv2[b][c2][N]
__global__ __launch_bounds__(256) void attn_pv_kernel()
{
    __shared__ float r0[64 * SV_S], r1[64 * SQ_S];
    int chunk = blockIdx.x, bh = blockIdx.y;
    int b = bh / NH_, h = bh % NH_;
    const float* v = g_qkv + ((size_t)b * 3 * C_ + 2 * C_ + (size_t)h * HD_) * N_ + chunk * NCW_;
    const float* P = g_P + (size_t)bh * 4096;
    uint32_t* hv2 = g_hv2 + ((size_t)b * 256 + h * 32) * N_ + chunk * NCW_;

    int tid = threadIdx.x, lane = tid & 31, wid = tid >> 5;
    int gid = lane >> 2, tig = lane & 3;
    int m_warp = (wid & 3) * 16, n_warp = (wid >> 2) * 32;

    for (int i = tid * 4; i < 4096; i += 1024) {
        int row = i >> 6, col = i & 63;
        *(float4*)(r1 + row * SQ_S + col) = *(const float4*)(P + i);
    }
    float4 rv[4];
    #pragma unroll
    for (int l = 0; l < 4; l++) {
        int idx = tid + l * 256, row = idx >> 4, c4 = idx & 15;
        rv[l] = *(const float4*)(v + (size_t)row * N_ + c4 * 4);
    }
    __syncthreads();

    for (int n0 = 0; n0 < NCW_; n0 += 64) {
        #pragma unroll
        for (int l = 0; l < 4; l++) {
            int idx = tid + l * 256, row = idx >> 4, c4 = idx & 15;
            *(float4*)(r0 + row * SV_S + c4 * 4) = rv[l];
        }
        __syncthreads();
        if (n0 + 64 < NCW_) {
            #pragma unroll
            for (int l = 0; l < 4; l++) {
                int idx = tid + l * 256, row = idx >> 4, c4 = idx & 15;
                rv[l] = *(const float4*)(v + (size_t)row * N_ + n0 + 64 + c4 * 4);
            }
        }
        float a2[4][4];
        #pragma unroll
        for (int nt = 0; nt < 4; nt++)
            #pragma unroll
            for (int r = 0; r < 4; r++) a2[nt][r] = 0.f;
        #pragma unroll
        for (int ks = 0; ks < 8; ks++) {
            int kb = ks * 8;
            float a0 = r1[(m_warp+gid)*SQ_S + kb + tig];
            float a1 = r1[(m_warp+gid+8)*SQ_S + kb + tig];
            float a2f = r1[(m_warp+gid)*SQ_S + kb + tig + 4];
            float a3 = r1[(m_warp+gid+8)*SQ_S + kb + tig + 4];
            float bf[4][2];
            #pragma unroll
            for (int nt = 0; nt < 4; nt++) {
                int nn = n_warp + nt * 8 + gid;
                bf[nt][0] = r0[(kb+tig)*SV_S + nn];
                bf[nt][1] = r0[(kb+tig+4)*SV_S + nn];
            }
            #pragma unroll
            for (int nt = 0; nt < 4; nt++)
                mma8(a2[nt], a0, a1, a2f, a3, bf[nt][0], bf[nt][1]);
        }
        __syncthreads();   // v reads done; reuse r0 as result stage, stride 66 (even)
        #pragma unroll
        for (int nt = 0; nt < 4; nt++) {
            int col = n_warp + nt * 8 + tig * 2, rA = m_warp + gid;
            *(float2*)(r0 + rA * 66 + col)       = make_float2(a2[nt][0], a2[nt][1]);
            *(float2*)(r0 + (rA + 8) * 66 + col) = make_float2(a2[nt][2], a2[nt][3]);
        }
        __syncthreads();
        int n = tid & 63, c2b = tid >> 6;
        #pragma unroll
        for (int j = 0; j < 8; j++) {
            int c2 = c2b + j * 4;
            hv2[(size_t)c2 * N_ + n0 + n] =
                packbf2(r0[(2*c2) * 66 + n], r0[(2*c2+1) * 66 + n]);
        }
        __syncthreads();
    }
}

// ---------------------------------------------------------------------------
extern "C" void kernel_launch(void* const* d_in, const int* in_sizes, int n_in,
                              void* d_out, int out_size)
{
    const float* x     = (const float*)d_in[0];
    const float* gamma = (const float*)d_in[1];
    const float* beta  = (const float*)d_in[2];
    const float* w_qkv = (const float*)d_in[3];
    const float* b_qkv = (const float*)d_in[4];
    const float* w_out = (const float*)d_in[5];
    const float* b_out = (const float*)d_in[6];
    float* out = (float*)d_out;

    cvt_wo_kernel<<<(C_ * C_ / 2 + 255) / 256, 256>>>(w_out);
    gn_stats_kernel<<<B_ * NG_, 256>>>(x, gamma, beta);
    wscale_kernel<<<dim3(3 * C_ / 16, B_), 256>>>(w_qkv, b_qkv);
    gemm_qkv<<<dim3(N_ / 128, (3 * C_) / 128, B_), 256>>>(x);
    attn_qk_kernel<<<dim3(NCH_, B_ * NH_), 256>>>();
    attn_softmax_kernel<<<B_ * NH_, 256>>>();
    attn_pv_kernel<<<dim3(NCH_, B_ * NH_), 256>>>();
    gemm_out<<<dim3(N_ / 128, C_ / 128, B_), 256>>>(b_out, x, out);
}